// round 2
// baseline (speedup 1.0000x reference)
#include <cuda_runtime.h>
#include <math.h>

// Problem constants
#define BB 2
#define LL 4096
#define DD 1024
#define HH 16
#define DKK 64
#define BH (BB*HH)          // 32
#define TOK (BB*LL)         // 8192

// ---------------- scratch (static device memory; no allocations) -------------
__device__ float g_q[TOK*DD];
__device__ float g_k[TOK*DD];     // becomes k_beta
__device__ float g_v[TOK*DD];     // becomes v_scaled
__device__ float g_o[TOK*DD];
__device__ float g_beta[BH*LL];
__device__ float g_lf[BH*LL];     // log(fast_decay+1e-6)
__device__ float g_ls[BH*LL];
__device__ float g_fw[BH*LL];     // pass1: cumsum, pass2: weights
__device__ float g_sw[BH*LL];
__device__ float g_alpha[BH*LL];
__device__ float g_rden[BH*2];
__device__ float g_M[BH*2*DKK*DKK];   // [bh][fast/slow][64][64]

__device__ __forceinline__ float sigmoidf_(float x) { return 1.0f/(1.0f+expf(-x)); }

// ---------------- SGEMM: C[M,N] = A[M,K] * B[K,N], row-major ----------------
// 128x128 tile, BK=8, 256 threads, 8x8 micro-tile per thread.
__global__ __launch_bounds__(256) void sgemm128(const float* __restrict__ A,
                                                const float* __restrict__ B,
                                                float* __restrict__ C,
                                                int M, int N, int K) {
    __shared__ __align__(16) float As[8][128];
    __shared__ __align__(16) float Bs[8][128];
    const int tid = threadIdx.x;
    const int crow = blockIdx.y * 128;
    const int ccol = blockIdx.x * 128;

    const int tr = (tid / 16) * 8;
    const int tc = (tid % 16) * 8;

    const int arow = tid / 2;            // 0..127
    const int acol = (tid % 2) * 4;      // 0 or 4
    const int brow = tid / 32;           // 0..7
    const int bcol = (tid % 32) * 4;     // 0..124

    float acc[8][8];
    #pragma unroll
    for (int i = 0; i < 8; i++)
        #pragma unroll
        for (int j = 0; j < 8; j++) acc[i][j] = 0.0f;

    for (int k0 = 0; k0 < K; k0 += 8) {
        float4 a = *(const float4*)&A[(crow + arow) * K + k0 + acol];
        As[acol + 0][arow] = a.x;
        As[acol + 1][arow] = a.y;
        As[acol + 2][arow] = a.z;
        As[acol + 3][arow] = a.w;
        *(float4*)&Bs[brow][bcol] = *(const float4*)&B[(k0 + brow) * N + ccol + bcol];
        __syncthreads();

        #pragma unroll
        for (int kk = 0; kk < 8; kk++) {
            float ar[8], br[8];
            *(float4*)&ar[0] = *(const float4*)&As[kk][tr];
            *(float4*)&ar[4] = *(const float4*)&As[kk][tr + 4];
            *(float4*)&br[0] = *(const float4*)&Bs[kk][tc];
            *(float4*)&br[4] = *(const float4*)&Bs[kk][tc + 4];
            #pragma unroll
            for (int i = 0; i < 8; i++)
                #pragma unroll
                for (int j = 0; j < 8; j++) acc[i][j] += ar[i] * br[j];
        }
        __syncthreads();
    }
    #pragma unroll
    for (int i = 0; i < 8; i++) {
        #pragma unroll
        for (int j = 0; j < 8; j += 4) {
            *(float4*)&C[(crow + tr + i) * N + ccol + tc + j] =
                make_float4(acc[i][j], acc[i][j+1], acc[i][j+2], acc[i][j+3]);
        }
    }
}

// ---------------- small projections: beta, fast/slow log-gates ---------------
__global__ __launch_bounds__(64) void proj_kernel(const float* __restrict__ x,
                                                  const float* __restrict__ Wb,
                                                  const float* __restrict__ Wfd,
                                                  const float* __restrict__ bfd,
                                                  const float* __restrict__ Wsd,
                                                  const float* __restrict__ bsd) {
    const int token = blockIdx.x;
    const int b = token / LL, l = token % LL;
    __shared__ float xs[DD];
    const int tid = threadIdx.x;
    const float4* xr = (const float4*)&x[(size_t)token * DD];
    #pragma unroll
    for (int i = tid; i < DD/4; i += 64) ((float4*)xs)[i] = xr[i];
    __syncthreads();

    if (tid < 48) {
        const int mat = tid >> 4, h = tid & 15;
        const float* W = (mat == 0) ? Wb : (mat == 1) ? Wfd : Wsd;
        float acc = 0.0f;
        #pragma unroll 8
        for (int d = 0; d < DD; d++) acc += xs[d] * W[d * HH + h];
        const int idx = (b * HH + h) * LL + l;
        if (mat == 0) {
            g_beta[idx] = sigmoidf_(acc);
        } else if (mat == 1) {
            g_lf[idx] = logf(sigmoidf_(acc + bfd[h]) + 1e-6f);
        } else {
            g_ls[idx] = logf(sigmoidf_(acc + bsd[h]) + 1e-6f);
        }
    }
}

// ------- l2norm q,k ; k_beta ; v_scaled ; token-flux MLP -> alpha ------------
__global__ __launch_bounds__(64) void norm_kernel(const float* __restrict__ Wtf1,
                                                  const float* __restrict__ btf1,
                                                  const float* __restrict__ Wtf2,
                                                  const float* __restrict__ btf2) {
    const int bid = blockIdx.x;                 // token*H + h
    const int h = bid % HH;
    const int token = bid / HH;
    const int b = token / LL, l = token % LL;
    const size_t base = (size_t)token * DD + h * DKK;
    const int tid = threadIdx.x;                // 64

    __shared__ float red[64];
    __shared__ float skb[64];

    // q l2norm
    float qv = g_q[base + tid];
    red[tid] = qv * qv; __syncthreads();
    #pragma unroll
    for (int off = 32; off > 0; off >>= 1) {
        if (tid < off) red[tid] += red[tid + off];
        __syncthreads();
    }
    const float qn = qv / fmaxf(sqrtf(red[0]), 1e-12f);
    __syncthreads();

    // k l2norm
    float kv = g_k[base + tid];
    red[tid] = kv * kv; __syncthreads();
    #pragma unroll
    for (int off = 32; off > 0; off >>= 1) {
        if (tid < off) red[tid] += red[tid + off];
        __syncthreads();
    }
    const float bet = g_beta[(b * HH + h) * LL + l];
    const float kb = (kv / fmaxf(sqrtf(red[0]), 1e-12f)) * bet;

    g_q[base + tid] = qn;
    g_k[base + tid] = kb;
    g_v[base + tid] = g_v[base + tid] * bet;
    skb[tid] = kb;
    __syncthreads();

    // token flux MLP: 64 -> 32 (silu) -> 1 (sigmoid), clip, alpha
    if (tid < 32) {
        float acc = btf1[tid];
        #pragma unroll
        for (int d = 0; d < 64; d++) acc += skb[d] * Wtf1[d * 32 + tid];
        acc = acc * sigmoidf_(acc);             // silu
        float p = acc * Wtf2[tid];
        #pragma unroll
        for (int off = 16; off > 0; off >>= 1) p += __shfl_down_sync(0xffffffffu, p, off);
        if (tid == 0) {
            float t = sigmoidf_(p + btf2[0]);
            t = fminf(fmaxf(t, 0.01f), 0.99f);
            g_alpha[(b * HH + h) * LL + l] = 0.5f + 0.3f * t;
        }
    }
}

// --------------- per-(b,h) log-cumsum scan -> decay weights ------------------
__global__ __launch_bounds__(256) void scan_kernel() {
    const int bh = blockIdx.x;
    const int tid = threadIdx.x;
    __shared__ float sf[256], ss[256];
    const float* lfp = g_lf + (size_t)bh * LL;
    const float* lsp = g_ls + (size_t)bh * LL;
    float* fwp = g_fw + (size_t)bh * LL;
    float* swp = g_sw + (size_t)bh * LL;

    float cf = 0.0f, cs = 0.0f;
    for (int c = 0; c < LL; c += 256) {
        sf[tid] = lfp[c + tid];
        ss[tid] = lsp[c + tid];
        __syncthreads();
        for (int off = 1; off < 256; off <<= 1) {
            float tf = 0.0f, ts = 0.0f;
            if (tid >= off) { tf = sf[tid - off]; ts = ss[tid - off]; }
            __syncthreads();
            sf[tid] += tf; ss[tid] += ts;
            __syncthreads();
        }
        fwp[c + tid] = sf[tid] + cf;    // inclusive cumsum (temp)
        swp[c + tid] = ss[tid] + cs;
        cf += sf[255];
        cs += ss[255];
        __syncthreads();
    }
    const float totf = cf, tots = cs;

    float sumf = 0.0f, sums = 0.0f;
    for (int c = 0; c < LL; c += 256) {
        float f = expf(totf - fwp[c + tid]);
        float s = expf(tots - swp[c + tid]);
        fwp[c + tid] = f;
        swp[c + tid] = s;
        sumf += f; sums += s;
    }
    sf[tid] = sumf; ss[tid] = sums; __syncthreads();
    #pragma unroll
    for (int off = 128; off > 0; off >>= 1) {
        if (tid < off) { sf[tid] += sf[tid + off]; ss[tid] += ss[tid + off]; }
        __syncthreads();
    }
    if (tid == 0) {
        g_rden[bh * 2 + 0] = 1.0f / (sf[0] + 1e-6f);
        g_rden[bh * 2 + 1] = 1.0f / (ss[0] + 1e-6f);
    }
}

// ---------------- zero the M accumulators ------------------------------------
__global__ void zeroM_kernel() {
    int i = blockIdx.x * blockDim.x + threadIdx.x;
    if (i < BH * 2 * DKK * DKK) g_M[i] = 0.0f;
}

// ---------------- M_fast / M_slow accumulation (KV outer products) -----------
#define MCHUNKS 8
__global__ __launch_bounds__(256) void mstate_kernel() {
    const int bh = blockIdx.y;
    const int chunk = blockIdx.x;
    const int b = bh / HH, h = bh % HH;
    const int l0 = chunk * (LL / MCHUNKS);
    const int tid = threadIdx.x;

    __shared__ __align__(16) float skb[16][64];
    __shared__ __align__(16) float sv[16][64];
    __shared__ float sfw[16], ssw[16];

    float accf[4][4], accs[4][4];
    #pragma unroll
    for (int i = 0; i < 4; i++)
        #pragma unroll
        for (int j = 0; j < 4; j++) { accf[i][j] = 0.0f; accs[i][j] = 0.0f; }

    const int tr = (tid / 16) * 4, tc = (tid % 16) * 4;
    const int r = (tid * 4) >> 6, cc = (tid * 4) & 63;

    for (int lc = 0; lc < LL / MCHUNKS; lc += 16) {
        const int l = l0 + lc + r;
        *(float4*)&skb[r][cc] = *(const float4*)&g_k[((size_t)b * LL + l) * DD + h * DKK + cc];
        *(float4*)&sv[r][cc]  = *(const float4*)&g_v[((size_t)b * LL + l) * DD + h * DKK + cc];
        if (tid < 16) {
            sfw[tid] = g_fw[(size_t)bh * LL + l0 + lc + tid];
            ssw[tid] = g_sw[(size_t)bh * LL + l0 + lc + tid];
        }
        __syncthreads();
        #pragma unroll
        for (int kk = 0; kk < 16; kk++) {
            const float wf = sfw[kk], ws = ssw[kk];
            float kf[4], ks[4], vv[4];
            #pragma unroll
            for (int i = 0; i < 4; i++) {
                float kv = skb[kk][tr + i];
                kf[i] = kv * wf; ks[i] = kv * ws;
            }
            #pragma unroll
            for (int j = 0; j < 4; j++) vv[j] = sv[kk][tc + j];
            #pragma unroll
            for (int i = 0; i < 4; i++)
                #pragma unroll
                for (int j = 0; j < 4; j++) {
                    accf[i][j] += kf[i] * vv[j];
                    accs[i][j] += ks[i] * vv[j];
                }
        }
        __syncthreads();
    }
    float* Mf = g_M + (size_t)bh * 2 * DKK * DKK;
    float* Ms = Mf + DKK * DKK;
    #pragma unroll
    for (int i = 0; i < 4; i++)
        #pragma unroll
        for (int j = 0; j < 4; j++) {
            atomicAdd(&Mf[(tr + i) * DKK + tc + j], accf[i][j]);
            atomicAdd(&Ms[(tr + i) * DKK + tc + j], accs[i][j]);
        }
}

// ---------------- per-token output: alpha*q@Mf + (1-alpha)*q@Ms --------------
__global__ __launch_bounds__(256) void out_kernel() {
    const int bh = blockIdx.y;
    const int b = bh / HH, h = bh % HH;
    const int lbase = blockIdx.x * 128;
    const int tid = threadIdx.x;

    __shared__ __align__(16) float Mf[DKK * DKK];
    __shared__ __align__(16) float Ms[DKK * DKK];
    __shared__ float qb[256];

    const float rf = g_rden[bh * 2 + 0], rs = g_rden[bh * 2 + 1];
    const float* Mg = g_M + (size_t)bh * 2 * DKK * DKK;
    for (int i = tid; i < DKK * DKK; i += 256) {
        Mf[i] = Mg[i] * rf;
        Ms[i] = Mg[DKK * DKK + i] * rs;
    }
    __syncthreads();

    const int sub = tid >> 6, e = tid & 63;
    for (int t = 0; t < 32; t++) {
        const int l = lbase + t * 4 + sub;
        qb[tid] = g_q[((size_t)b * LL + l) * DD + h * DKK + e];
        __syncthreads();
        float sfv = 0.0f, ssv = 0.0f;
        #pragma unroll
        for (int d = 0; d < 64; d++) {
            const float qd = qb[sub * 64 + d];
            sfv += qd * Mf[d * 64 + e];
            ssv += qd * Ms[d * 64 + e];
        }
        const float a = g_alpha[(size_t)bh * LL + l];
        g_o[((size_t)b * LL + l) * DD + h * DKK + e] = a * sfv + (1.0f - a) * ssv;
        __syncthreads();
    }
}

// -----------------------------------------------------------------------------
extern "C" void kernel_launch(void* const* d_in, const int* in_sizes, int n_in,
                              void* d_out, int out_size) {
    const float* x    = (const float*)d_in[0];
    const float* Wq   = (const float*)d_in[1];
    const float* Wk   = (const float*)d_in[2];
    const float* Wv   = (const float*)d_in[3];
    const float* Wb   = (const float*)d_in[4];
    const float* Wo   = (const float*)d_in[5];
    const float* Wfd  = (const float*)d_in[6];
    const float* bfd  = (const float*)d_in[7];
    const float* Wsd  = (const float*)d_in[8];
    const float* bsd  = (const float*)d_in[9];
    const float* Wtf1 = (const float*)d_in[10];
    const float* btf1 = (const float*)d_in[11];
    const float* Wtf2 = (const float*)d_in[12];
    const float* btf2 = (const float*)d_in[13];
    float* out = (float*)d_out;

    float *q_, *k_, *v_, *o_;
    cudaGetSymbolAddress((void**)&q_, g_q);
    cudaGetSymbolAddress((void**)&k_, g_k);
    cudaGetSymbolAddress((void**)&v_, g_v);
    cudaGetSymbolAddress((void**)&o_, g_o);

    dim3 gGemm(DD / 128, TOK / 128);   // (8, 64)

    // 1) big projections
    sgemm128<<<gGemm, 256>>>(x, Wq, q_, TOK, DD, DD);
    sgemm128<<<gGemm, 256>>>(x, Wk, k_, TOK, DD, DD);
    sgemm128<<<gGemm, 256>>>(x, Wv, v_, TOK, DD, DD);

    // 2) gate projections
    proj_kernel<<<TOK, 64>>>(x, Wb, Wfd, bfd, Wsd, bsd);

    // 3) l2norm + k_beta + v_scaled + token-flux alpha
    norm_kernel<<<TOK * HH, 64>>>(Wtf1, btf1, Wtf2, btf2);

    // 4) decay scan
    scan_kernel<<<BH, 256>>>();

    // 5) KV state accumulation
    zeroM_kernel<<<(BH * 2 * DKK * DKK + 255) / 256, 256>>>();
    mstate_kernel<<<dim3(MCHUNKS, BH), 256>>>();

    // 6) output blend
    out_kernel<<<dim3(LL / 128, BH), 256>>>();

    // 7) final projection
    sgemm128<<<gGemm, 256>>>(o_, Wo, out, TOK, DD, DD);
}

// round 4
// speedup vs baseline: 2.5022x; 2.5022x over previous
#include <cuda_runtime.h>
#include <math.h>
#include <stdint.h>

// Problem constants
#define BB 2
#define LL 4096
#define DD 1024
#define HH 16
#define DKK 64
#define BH (BB*HH)          // 32
#define TOK (BB*LL)         // 8192

// ---------------- scratch (static device memory; no allocations) -------------
__device__ float g_q[TOK*DD];
__device__ float g_k[TOK*DD];     // becomes k_beta
__device__ float g_v[TOK*DD];     // becomes v_scaled
__device__ float g_o[TOK*DD];
__device__ float g_gate[TOK*128]; // x @ Wcat  (cols: 0-15 beta, 16-31 fast, 32-47 slow)
__device__ float g_wcat[DD*128];  // packed [Wb | Wfd | Wsd | 0] as [K][128]
__device__ float g_beta[BH*LL];
__device__ float g_lf[BH*LL];
__device__ float g_ls[BH*LL];
__device__ float g_fw[BH*LL];
__device__ float g_sw[BH*LL];
__device__ float g_alpha[BH*LL];
__device__ float g_rden[BH*2];
__device__ float g_M[BH*2*DKK*DKK];

__device__ __forceinline__ float sigmoidf_(float x) { return 1.0f/(1.0f+expf(-x)); }
__device__ __forceinline__ uint32_t f2tf32(float x) {
    uint32_t r; asm("cvt.rna.tf32.f32 %0, %1;" : "=r"(r) : "f"(x)); return r;
}

// =========================== tf32 mma.sync GEMM ==============================
// C[M,N] = A[M,K=1024] * W[K=1024,N], all row-major fp32, tf32 compute.
// Tile 128x128, BK=16, 256 threads (8 warps), warp tile 32(m) x 64(n).
#define ASTRIDE 20     // floats per A smem row (bank-conflict-free frags)
#define BSTRIDE 136    // floats per B smem row
#define NKITER (DD/16) // 64

__device__ __forceinline__ void mma8(float* c, const uint32_t* a, const uint32_t* b) {
    asm volatile(
        "mma.sync.aligned.m16n8k8.row.col.f32.tf32.tf32.f32 "
        "{%0,%1,%2,%3}, {%4,%5,%6,%7}, {%8,%9}, {%0,%1,%2,%3};"
        : "+f"(c[0]), "+f"(c[1]), "+f"(c[2]), "+f"(c[3])
        : "r"(a[0]), "r"(a[1]), "r"(a[2]), "r"(a[3]), "r"(b[0]), "r"(b[1]));
}

__device__ __forceinline__ void gemm_body(const float* __restrict__ A,
                                          const float* __restrict__ W,
                                          float* __restrict__ C, int N) {
    __shared__ __align__(16) float As[2][128*ASTRIDE];
    __shared__ __align__(16) float Bs[2][16*BSTRIDE];

    const int tid = threadIdx.x;
    const int lane = tid & 31;
    const int wid = tid >> 5;
    const int g = lane >> 2, t4 = lane & 3;
    const int mbase = (wid & 3) * 32;
    const int nbase = (wid >> 2) * 64;
    const int crow = blockIdx.y * 128;
    const int ccol = blockIdx.x * 128;

    // global->smem coords
    const int ar = tid >> 2;            // A row (and +64)
    const int akc = (tid & 3) * 4;      // A k offset within 16
    const int bk = tid >> 5;            // B k row (and +8)
    const int bc = lane * 4;            // B col offset within 128

    float acc[2][8][4];
    #pragma unroll
    for (int i = 0; i < 2; i++)
        #pragma unroll
        for (int j = 0; j < 8; j++)
            #pragma unroll
            for (int c = 0; c < 4; c++) acc[i][j][c] = 0.0f;

    // ---- prologue: tile 0 -> smem[0]
    {
        float4 a0 = *(const float4*)&A[(size_t)(crow + ar) * DD + akc];
        float4 a1 = *(const float4*)&A[(size_t)(crow + ar + 64) * DD + akc];
        float4 b0 = *(const float4*)&W[(size_t)bk * N + ccol + bc];
        float4 b1 = *(const float4*)&W[(size_t)(bk + 8) * N + ccol + bc];
        uint4 u;
        u.x=f2tf32(a0.x); u.y=f2tf32(a0.y); u.z=f2tf32(a0.z); u.w=f2tf32(a0.w);
        *(uint4*)&As[0][ar*ASTRIDE + akc] = u;
        u.x=f2tf32(a1.x); u.y=f2tf32(a1.y); u.z=f2tf32(a1.z); u.w=f2tf32(a1.w);
        *(uint4*)&As[0][(ar+64)*ASTRIDE + akc] = u;
        u.x=f2tf32(b0.x); u.y=f2tf32(b0.y); u.z=f2tf32(b0.z); u.w=f2tf32(b0.w);
        *(uint4*)&Bs[0][bk*BSTRIDE + bc] = u;
        u.x=f2tf32(b1.x); u.y=f2tf32(b1.y); u.z=f2tf32(b1.z); u.w=f2tf32(b1.w);
        *(uint4*)&Bs[0][(bk+8)*BSTRIDE + bc] = u;
    }
    __syncthreads();

    for (int it = 0; it < NKITER; it++) {
        const int buf = it & 1;
        float4 na0, na1, nb0, nb1;
        if (it + 1 < NKITER) {
            const int k0 = (it + 1) * 16;
            na0 = *(const float4*)&A[(size_t)(crow + ar) * DD + k0 + akc];
            na1 = *(const float4*)&A[(size_t)(crow + ar + 64) * DD + k0 + akc];
            nb0 = *(const float4*)&W[(size_t)(k0 + bk) * N + ccol + bc];
            nb1 = *(const float4*)&W[(size_t)(k0 + bk + 8) * N + ccol + bc];
        }

        const float* as = As[buf];
        const float* bs = Bs[buf];
        #pragma unroll
        for (int ks = 0; ks < 2; ks++) {
            const int kk = ks * 8;
            uint32_t af[2][4];
            #pragma unroll
            for (int i = 0; i < 2; i++) {
                const int r0 = (mbase + i * 16 + g) * ASTRIDE;
                af[i][0] = __float_as_uint(as[r0 + kk + t4]);
                af[i][1] = __float_as_uint(as[r0 + 8 * ASTRIDE + kk + t4]);
                af[i][2] = __float_as_uint(as[r0 + kk + t4 + 4]);
                af[i][3] = __float_as_uint(as[r0 + 8 * ASTRIDE + kk + t4 + 4]);
            }
            uint32_t bf[8][2];
            #pragma unroll
            for (int j = 0; j < 8; j++) {
                const int c0 = nbase + j * 8 + g;
                bf[j][0] = __float_as_uint(bs[(kk + t4) * BSTRIDE + c0]);
                bf[j][1] = __float_as_uint(bs[(kk + t4 + 4) * BSTRIDE + c0]);
            }
            #pragma unroll
            for (int i = 0; i < 2; i++)
                #pragma unroll
                for (int j = 0; j < 8; j++) mma8(acc[i][j], af[i], bf[j]);
        }
        __syncthreads();

        if (it + 1 < NKITER) {
            const int nb = buf ^ 1;
            uint4 u;
            u.x=f2tf32(na0.x); u.y=f2tf32(na0.y); u.z=f2tf32(na0.z); u.w=f2tf32(na0.w);
            *(uint4*)&As[nb][ar*ASTRIDE + akc] = u;
            u.x=f2tf32(na1.x); u.y=f2tf32(na1.y); u.z=f2tf32(na1.z); u.w=f2tf32(na1.w);
            *(uint4*)&As[nb][(ar+64)*ASTRIDE + akc] = u;
            u.x=f2tf32(nb0.x); u.y=f2tf32(nb0.y); u.z=f2tf32(nb0.z); u.w=f2tf32(nb0.w);
            *(uint4*)&Bs[nb][bk*BSTRIDE + bc] = u;
            u.x=f2tf32(nb1.x); u.y=f2tf32(nb1.y); u.z=f2tf32(nb1.z); u.w=f2tf32(nb1.w);
            *(uint4*)&Bs[nb][(bk+8)*BSTRIDE + bc] = u;
            __syncthreads();
        }
    }

    // ---- epilogue
    #pragma unroll
    for (int i = 0; i < 2; i++) {
        const int row = crow + mbase + i * 16 + g;
        #pragma unroll
        for (int j = 0; j < 8; j++) {
            const int col = ccol + nbase + j * 8 + t4 * 2;
            *(float2*)&C[(size_t)row * N + col] = make_float2(acc[i][j][0], acc[i][j][1]);
            *(float2*)&C[(size_t)(row + 8) * N + col] = make_float2(acc[i][j][2], acc[i][j][3]);
        }
    }
}

__global__ __launch_bounds__(256, 2) void gemm_qkv(const float* __restrict__ x,
                                                   const float* __restrict__ Wq,
                                                   const float* __restrict__ Wk,
                                                   const float* __restrict__ Wv) {
    const float* W = (blockIdx.z == 0) ? Wq : (blockIdx.z == 1) ? Wk : Wv;
    float* C = (blockIdx.z == 0) ? g_q : (blockIdx.z == 1) ? g_k : g_v;
    gemm_body(x, W, C, DD);
}

__global__ __launch_bounds__(256, 2) void gemm_one(const float* __restrict__ A,
                                                   const float* __restrict__ W,
                                                   float* __restrict__ C, int N) {
    gemm_body(A, W, C, N);
}

// ---------------- pack gate weights: [Wb | Wfd | Wsd | 0] -> [K][128] --------
__global__ __launch_bounds__(256) void packW_kernel(const float* __restrict__ Wb,
                                                    const float* __restrict__ Wfd,
                                                    const float* __restrict__ Wsd) {
    const int i = blockIdx.x * 256 + threadIdx.x;   // over DD*128
    const int k = i >> 7, c = i & 127;
    float v = 0.0f;
    if (c < 16)      v = Wb [k * HH + c];
    else if (c < 32) v = Wfd[k * HH + (c - 16)];
    else if (c < 48) v = Wsd[k * HH + (c - 32)];
    g_wcat[i] = v;
}

// ---------------- gate elementwise: sigmoid / log gates, transpose -----------
__global__ __launch_bounds__(256) void gate_ew(const float* __restrict__ bfd,
                                               const float* __restrict__ bsd) {
    const int idx = blockIdx.x * 256 + threadIdx.x;  // bh*LL + l
    const int bh = idx >> 12;      // /LL
    const int l = idx & (LL - 1);
    const int b = bh >> 4, h = bh & 15;
    const float* row = g_gate + ((size_t)(b * LL + l)) * 128;
    g_beta[idx] = sigmoidf_(row[h]);
    g_lf[idx] = logf(sigmoidf_(row[16 + h] + bfd[h]) + 1e-6f);
    g_ls[idx] = logf(sigmoidf_(row[32 + h] + bsd[h]) + 1e-6f);
}

// ------- l2norm q,k ; k_beta ; v_scaled ; token-flux MLP -> alpha ------------
// warp per (token, head); 8 warps/block
__global__ __launch_bounds__(256) void norm_kernel(const float* __restrict__ Wtf1,
                                                   const float* __restrict__ btf1,
                                                   const float* __restrict__ Wtf2,
                                                   const float* __restrict__ btf2) {
    const int w = threadIdx.x >> 5;
    const int lane = threadIdx.x & 31;
    const int gw = blockIdx.x * 8 + w;      // token*HH + h
    const int token = gw >> 4;
    const int h = gw & 15;
    const int b = token >> 12, l = token & (LL - 1);
    const size_t base = (size_t)token * DD + h * DKK;
    const int gidx = (b * HH + h) * LL + l;

    float q0 = g_q[base + lane], q1 = g_q[base + 32 + lane];
    float s = q0 * q0 + q1 * q1;
    #pragma unroll
    for (int off = 16; off > 0; off >>= 1) s += __shfl_xor_sync(0xffffffffu, s, off);
    const float rq = 1.0f / fmaxf(sqrtf(s), 1e-12f);

    float k0 = g_k[base + lane], k1 = g_k[base + 32 + lane];
    float s2 = k0 * k0 + k1 * k1;
    #pragma unroll
    for (int off = 16; off > 0; off >>= 1) s2 += __shfl_xor_sync(0xffffffffu, s2, off);
    const float rk = 1.0f / fmaxf(sqrtf(s2), 1e-12f);

    const float bet = g_beta[gidx];
    const float kb0 = k0 * rk * bet, kb1 = k1 * rk * bet;

    g_q[base + lane] = q0 * rq;
    g_q[base + 32 + lane] = q1 * rq;
    g_k[base + lane] = kb0;
    g_k[base + 32 + lane] = kb1;
    g_v[base + lane] *= bet;
    g_v[base + 32 + lane] *= bet;

    __shared__ float skb[8][64];
    skb[w][lane] = kb0;
    skb[w][lane + 32] = kb1;
    __syncwarp();

    // token flux MLP: 64 -> 32 silu -> 1 sigmoid
    float acc = btf1[lane];
    #pragma unroll 8
    for (int d = 0; d < 64; d++) acc += skb[w][d] * Wtf1[d * 32 + lane];
    acc = acc * sigmoidf_(acc);
    float p = acc * Wtf2[lane];
    #pragma unroll
    for (int off = 16; off > 0; off >>= 1) p += __shfl_xor_sync(0xffffffffu, p, off);
    if (lane == 0) {
        float t = sigmoidf_(p + btf2[0]);
        t = fminf(fmaxf(t, 0.01f), 0.99f);
        g_alpha[gidx] = 0.5f + 0.3f * t;
    }
}

// --------------- per-(b,h) log-cumsum scan -> decay weights ------------------
__global__ __launch_bounds__(256) void scan_kernel() {
    const int bh = blockIdx.x;
    const int tid = threadIdx.x;
    __shared__ float sf[256], ss[256];
    const float* lfp = g_lf + (size_t)bh * LL;
    const float* lsp = g_ls + (size_t)bh * LL;
    float* fwp = g_fw + (size_t)bh * LL;
    float* swp = g_sw + (size_t)bh * LL;

    float cf = 0.0f, cs = 0.0f;
    for (int c = 0; c < LL; c += 256) {
        sf[tid] = lfp[c + tid];
        ss[tid] = lsp[c + tid];
        __syncthreads();
        for (int off = 1; off < 256; off <<= 1) {
            float tf = 0.0f, ts = 0.0f;
            if (tid >= off) { tf = sf[tid - off]; ts = ss[tid - off]; }
            __syncthreads();
            sf[tid] += tf; ss[tid] += ts;
            __syncthreads();
        }
        fwp[c + tid] = sf[tid] + cf;
        swp[c + tid] = ss[tid] + cs;
        cf += sf[255];
        cs += ss[255];
        __syncthreads();
    }
    const float totf = cf, tots = cs;

    float sumf = 0.0f, sums = 0.0f;
    for (int c = 0; c < LL; c += 256) {
        float f = expf(totf - fwp[c + tid]);
        float s = expf(tots - swp[c + tid]);
        fwp[c + tid] = f;
        swp[c + tid] = s;
        sumf += f; sums += s;
    }
    sf[tid] = sumf; ss[tid] = sums; __syncthreads();
    #pragma unroll
    for (int off = 128; off > 0; off >>= 1) {
        if (tid < off) { sf[tid] += sf[tid + off]; ss[tid] += ss[tid + off]; }
        __syncthreads();
    }
    if (tid == 0) {
        g_rden[bh * 2 + 0] = 1.0f / (sf[0] + 1e-6f);
        g_rden[bh * 2 + 1] = 1.0f / (ss[0] + 1e-6f);
    }
}

// ---------------- zero the M accumulators ------------------------------------
__global__ void zeroM_kernel() {
    int i = blockIdx.x * blockDim.x + threadIdx.x;
    if (i < BH * 2 * DKK * DKK) g_M[i] = 0.0f;
}

// ---------------- M_fast / M_slow accumulation (KV outer products) -----------
#define MCHUNKS 8
__global__ __launch_bounds__(256) void mstate_kernel() {
    const int bh = blockIdx.y;
    const int chunk = blockIdx.x;
    const int b = bh / HH, h = bh % HH;
    const int l0 = chunk * (LL / MCHUNKS);
    const int tid = threadIdx.x;

    __shared__ __align__(16) float skb[16][64];
    __shared__ __align__(16) float sv[16][64];
    __shared__ float sfw[16], ssw[16];

    float accf[4][4], accs[4][4];
    #pragma unroll
    for (int i = 0; i < 4; i++)
        #pragma unroll
        for (int j = 0; j < 4; j++) { accf[i][j] = 0.0f; accs[i][j] = 0.0f; }

    const int tr = (tid / 16) * 4, tc = (tid % 16) * 4;
    const int r = (tid * 4) >> 6, cc = (tid * 4) & 63;

    for (int lc = 0; lc < LL / MCHUNKS; lc += 16) {
        const int l = l0 + lc + r;
        *(float4*)&skb[r][cc] = *(const float4*)&g_k[((size_t)b * LL + l) * DD + h * DKK + cc];
        *(float4*)&sv[r][cc]  = *(const float4*)&g_v[((size_t)b * LL + l) * DD + h * DKK + cc];
        if (tid < 16) {
            sfw[tid] = g_fw[(size_t)bh * LL + l0 + lc + tid];
            ssw[tid] = g_sw[(size_t)bh * LL + l0 + lc + tid];
        }
        __syncthreads();
        #pragma unroll
        for (int kk = 0; kk < 16; kk++) {
            const float wf = sfw[kk], ws = ssw[kk];
            float kf[4], ks2[4], vv[4];
            #pragma unroll
            for (int i = 0; i < 4; i++) {
                float kv = skb[kk][tr + i];
                kf[i] = kv * wf; ks2[i] = kv * ws;
            }
            #pragma unroll
            for (int j = 0; j < 4; j++) vv[j] = sv[kk][tc + j];
            #pragma unroll
            for (int i = 0; i < 4; i++)
                #pragma unroll
                for (int j = 0; j < 4; j++) {
                    accf[i][j] += kf[i] * vv[j];
                    accs[i][j] += ks2[i] * vv[j];
                }
        }
        __syncthreads();
    }
    float* Mf = g_M + (size_t)bh * 2 * DKK * DKK;
    float* Ms = Mf + DKK * DKK;
    #pragma unroll
    for (int i = 0; i < 4; i++)
        #pragma unroll
        for (int j = 0; j < 4; j++) {
            atomicAdd(&Mf[(tr + i) * DKK + tc + j], accf[i][j]);
            atomicAdd(&Ms[(tr + i) * DKK + tc + j], accs[i][j]);
        }
}

// ---------------- per-token output: alpha*q@Mf + (1-alpha)*q@Ms --------------
__global__ __launch_bounds__(256) void out_kernel() {
    const int bh = blockIdx.y;
    const int b = bh / HH, h = bh % HH;
    const int lbase = blockIdx.x * 128;
    const int tid = threadIdx.x;

    __shared__ __align__(16) float Mf[DKK * DKK];
    __shared__ __align__(16) float Ms[DKK * DKK];
    __shared__ float qb[256];

    const float rf = g_rden[bh * 2 + 0], rs = g_rden[bh * 2 + 1];
    const float* Mg = g_M + (size_t)bh * 2 * DKK * DKK;
    for (int i = tid; i < DKK * DKK; i += 256) {
        Mf[i] = Mg[i] * rf;
        Ms[i] = Mg[DKK * DKK + i] * rs;
    }
    __syncthreads();

    const int sub = tid >> 6, e = tid & 63;
    for (int t = 0; t < 32; t++) {
        const int l = lbase + t * 4 + sub;
        qb[tid] = g_q[((size_t)b * LL + l) * DD + h * DKK + e];
        __syncthreads();
        float sfv = 0.0f, ssv = 0.0f;
        #pragma unroll
        for (int d = 0; d < 64; d++) {
            const float qd = qb[sub * 64 + d];
            sfv += qd * Mf[d * 64 + e];
            ssv += qd * Ms[d * 64 + e];
        }
        const float a = g_alpha[(size_t)bh * LL + l];
        g_o[((size_t)b * LL + l) * DD + h * DKK + e] = a * sfv + (1.0f - a) * ssv;
        __syncthreads();
    }
}

// -----------------------------------------------------------------------------
extern "C" void kernel_launch(void* const* d_in, const int* in_sizes, int n_in,
                              void* d_out, int out_size) {
    const float* x    = (const float*)d_in[0];
    const float* Wq   = (const float*)d_in[1];
    const float* Wk   = (const float*)d_in[2];
    const float* Wv   = (const float*)d_in[3];
    const float* Wb   = (const float*)d_in[4];
    const float* Wo   = (const float*)d_in[5];
    const float* Wfd  = (const float*)d_in[6];
    const float* bfd  = (const float*)d_in[7];
    const float* Wsd  = (const float*)d_in[8];
    const float* bsd  = (const float*)d_in[9];
    const float* Wtf1 = (const float*)d_in[10];
    const float* btf1 = (const float*)d_in[11];
    const float* Wtf2 = (const float*)d_in[12];
    const float* btf2 = (const float*)d_in[13];
    float* out = (float*)d_out;

    float *o_, *wcat_, *gate_;
    cudaGetSymbolAddress((void**)&o_, g_o);
    cudaGetSymbolAddress((void**)&wcat_, g_wcat);
    cudaGetSymbolAddress((void**)&gate_, g_gate);

    // 0) pack gate weights
    packW_kernel<<<(DD * 128) / 256, 256>>>(Wb, Wfd, Wsd);

    // 1) big projections q,k,v (tensor cores, tf32)
    gemm_qkv<<<dim3(DD / 128, TOK / 128, 3), 256>>>(x, Wq, Wk, Wv);

    // 2) gate projections as one GEMM (N=128) + elementwise
    gemm_one<<<dim3(1, TOK / 128, 1), 256>>>(x, wcat_, gate_, 128);
    gate_ew<<<(BH * LL) / 256, 256>>>(bfd, bsd);

    // 3) l2norm + k_beta + v_scaled + token-flux alpha
    norm_kernel<<<(TOK * HH) / 8, 256>>>(Wtf1, btf1, Wtf2, btf2);

    // 4) decay scan
    scan_kernel<<<BH, 256>>>();

    // 5) KV state accumulation
    zeroM_kernel<<<(BH * 2 * DKK * DKK + 255) / 256, 256>>>();
    mstate_kernel<<<dim3(MCHUNKS, BH), 256>>>();

    // 6) output blend
    out_kernel<<<dim3(LL / 128, BH), 256>>>();

    // 7) final projection
    gemm_one<<<dim3(DD / 128, TOK / 128, 1), 256>>>(o_, Wo, out, DD);
}

// round 5
// speedup vs baseline: 2.7183x; 1.0863x over previous
#include <cuda_runtime.h>
#include <math.h>
#include <stdint.h>

// Problem constants
#define BB 2
#define LL 4096
#define DD 1024
#define HH 16
#define DKK 64
#define BH (BB*HH)          // 32
#define TOK (BB*LL)         // 8192

// ---------------- scratch (static device memory; no allocations) -------------
__device__ float g_xr[TOK*DD];    // tf32-rounded x
__device__ float g_wr[4*DD*DD];   // tf32-rounded Wq,Wk,Wv,Wo
__device__ float g_q[TOK*DD];
__device__ float g_k[TOK*DD];     // becomes k_beta
__device__ float g_v[TOK*DD];     // becomes v_scaled
__device__ float g_o[TOK*DD];     // stored tf32-rounded
__device__ float g_gate[TOK*128];
__device__ float g_wcat[DD*128];  // packed [Wb | Wfd | Wsd | 0], tf32-rounded
__device__ float g_beta[BH*LL];
__device__ float g_lf[BH*LL];
__device__ float g_ls[BH*LL];
__device__ float g_fw[BH*LL];
__device__ float g_sw[BH*LL];
__device__ float g_alpha[BH*LL];
__device__ float g_rden[BH*2];
__device__ float g_M[BH*2*DKK*DKK];

__device__ __forceinline__ float sigmoidf_(float x) { return 1.0f/(1.0f+expf(-x)); }
__device__ __forceinline__ uint32_t f2tf32(float x) {
    uint32_t r; asm("cvt.rna.tf32.f32 %0, %1;" : "=r"(r) : "f"(x)); return r;
}
__device__ __forceinline__ uint32_t smem_u32(const void* p) {
    uint32_t a;
    asm("{ .reg .u64 t; cvta.to.shared.u64 t, %1; cvt.u32.u64 %0, t; }" : "=r"(a) : "l"(p));
    return a;
}
__device__ __forceinline__ void cp_async16(uint32_t dst, const void* src) {
    asm volatile("cp.async.cg.shared.global [%0], [%1], 16;" :: "r"(dst), "l"(src));
}
#define CP_COMMIT() asm volatile("cp.async.commit_group;" ::: "memory")
#define CP_WAIT(n)  asm volatile("cp.async.wait_group %0;" :: "n"(n) : "memory")

// =========================== tf32 mma.sync GEMM ==============================
// C[M,N] = A[M,K=1024] * W[K=1024,N]; A,W pre-rounded to tf32 bit patterns.
// Tile 128x128, BK=16, 3-stage cp.async, 256 threads, warp tile 32(m)x64(n).
#define AST 20         // A smem row stride (floats), conflict-free frag reads
#define BST 136        // B smem row stride (floats)
#define A_STG (128*AST)          // 2560 floats
#define B_STG (16*BST)           // 2176 floats
#define STG_FLOATS (A_STG + B_STG)  // 4736
#define GSTAGES 3
#define GSMEM_BYTES (GSTAGES*STG_FLOATS*4)   // 56832
#define NKITER (DD/16) // 64

__device__ __forceinline__ void mma8(float* c, const uint32_t* a, const uint32_t* b) {
    asm volatile(
        "mma.sync.aligned.m16n8k8.row.col.f32.tf32.tf32.f32 "
        "{%0,%1,%2,%3}, {%4,%5,%6,%7}, {%8,%9}, {%0,%1,%2,%3};"
        : "+f"(c[0]), "+f"(c[1]), "+f"(c[2]), "+f"(c[3])
        : "r"(a[0]), "r"(a[1]), "r"(a[2]), "r"(a[3]), "r"(b[0]), "r"(b[1]));
}

__device__ __forceinline__ void gemm_body(const float* __restrict__ A,
                                          const float* __restrict__ W,
                                          float* __restrict__ C, int N) {
    extern __shared__ float smp[];
    const uint32_t sbase = smem_u32(smp);

    const int tid = threadIdx.x;
    const int lane = tid & 31;
    const int wid = tid >> 5;
    const int g = lane >> 2, t4 = lane & 3;
    const int mbase = (wid & 3) * 32;
    const int nbase = (wid >> 2) * 64;
    const int crow = blockIdx.y * 128;
    const int ccol = blockIdx.x * 128;

    float acc[2][8][4];
    #pragma unroll
    for (int i = 0; i < 2; i++)
        #pragma unroll
        for (int j = 0; j < 8; j++)
            #pragma unroll
            for (int c = 0; c < 4; c++) acc[i][j][c] = 0.0f;

    // cp.async issue for one K-stage
    auto issue = [&](int it) {
        const int k0 = it * 16;
        const uint32_t abase = sbase + (uint32_t)((it % GSTAGES) * STG_FLOATS) * 4u;
        const uint32_t bbase = abase + A_STG * 4u;
        #pragma unroll
        for (int j = 0; j < 2; j++) {
            const int ch = tid + 256 * j;           // 0..511
            const int ar = ch >> 2, ac = (ch & 3) * 4;
            cp_async16(abase + (uint32_t)(ar * AST + ac) * 4u,
                       &A[(size_t)(crow + ar) * DD + k0 + ac]);
        }
        #pragma unroll
        for (int j = 0; j < 2; j++) {
            const int ch = tid + 256 * j;
            const int br = ch >> 5, bc = (ch & 31) * 4;
            cp_async16(bbase + (uint32_t)(br * BST + bc) * 4u,
                       &W[(size_t)(k0 + br) * N + ccol + bc]);
        }
    };

    issue(0); CP_COMMIT();
    issue(1); CP_COMMIT();

    for (int it = 0; it < NKITER; it++) {
        CP_WAIT(1);
        __syncthreads();
        if (it + 2 < NKITER) issue(it + 2);
        CP_COMMIT();

        const float* as = smp + (it % GSTAGES) * STG_FLOATS;
        const float* bs = as + A_STG;
        #pragma unroll
        for (int ks = 0; ks < 2; ks++) {
            const int kk = ks * 8;
            uint32_t af[2][4];
            #pragma unroll
            for (int i = 0; i < 2; i++) {
                const int r0 = (mbase + i * 16 + g) * AST;
                af[i][0] = __float_as_uint(as[r0 + kk + t4]);
                af[i][1] = __float_as_uint(as[r0 + 8 * AST + kk + t4]);
                af[i][2] = __float_as_uint(as[r0 + kk + t4 + 4]);
                af[i][3] = __float_as_uint(as[r0 + 8 * AST + kk + t4 + 4]);
            }
            uint32_t bf[8][2];
            #pragma unroll
            for (int j = 0; j < 8; j++) {
                const int c0 = nbase + j * 8 + g;
                bf[j][0] = __float_as_uint(bs[(kk + t4) * BST + c0]);
                bf[j][1] = __float_as_uint(bs[(kk + t4 + 4) * BST + c0]);
            }
            #pragma unroll
            for (int i = 0; i < 2; i++)
                #pragma unroll
                for (int j = 0; j < 8; j++) mma8(acc[i][j], af[i], bf[j]);
        }
    }

    // ---- epilogue
    #pragma unroll
    for (int i = 0; i < 2; i++) {
        const int row = crow + mbase + i * 16 + g;
        #pragma unroll
        for (int j = 0; j < 8; j++) {
            const int col = ccol + nbase + j * 8 + t4 * 2;
            *(float2*)&C[(size_t)row * N + col] = make_float2(acc[i][j][0], acc[i][j][1]);
            *(float2*)&C[(size_t)(row + 8) * N + col] = make_float2(acc[i][j][2], acc[i][j][3]);
        }
    }
}

__global__ __launch_bounds__(256, 2) void gemm_qkv() {
    const float* W = g_wr + (size_t)blockIdx.z * DD * DD;
    float* C = (blockIdx.z == 0) ? g_q : (blockIdx.z == 1) ? g_k : g_v;
    gemm_body(g_xr, W, C, DD);
}

__global__ __launch_bounds__(256, 2) void gemm_one(const float* __restrict__ A,
                                                   const float* __restrict__ W,
                                                   float* __restrict__ C, int N) {
    gemm_body(A, W, C, N);
}

// ---------------- tf32 pre-rounding prepasses --------------------------------
__global__ __launch_bounds__(256) void round_x(const float* __restrict__ x) {
    const int i = (blockIdx.x * 256 + threadIdx.x) * 4;
    float4 v = *(const float4*)&x[i];
    uint4 u;
    u.x = f2tf32(v.x); u.y = f2tf32(v.y); u.z = f2tf32(v.z); u.w = f2tf32(v.w);
    *(uint4*)&g_xr[i] = u;
}

__global__ __launch_bounds__(256) void round_W(const float* __restrict__ Wq,
                                               const float* __restrict__ Wk,
                                               const float* __restrict__ Wv,
                                               const float* __restrict__ Wo) {
    const int i = (blockIdx.x * 256 + threadIdx.x) * 4;
    const int m = i / (DD * DD), off = i % (DD * DD);
    const float* src = (m == 0) ? Wq : (m == 1) ? Wk : (m == 2) ? Wv : Wo;
    float4 v = *(const float4*)&src[off];
    uint4 u;
    u.x = f2tf32(v.x); u.y = f2tf32(v.y); u.z = f2tf32(v.z); u.w = f2tf32(v.w);
    *(uint4*)&g_wr[i] = u;
}

// pack gate weights [Wb | Wfd | Wsd | 0] -> [K][128], tf32-rounded
__global__ __launch_bounds__(256) void packW_kernel(const float* __restrict__ Wb,
                                                    const float* __restrict__ Wfd,
                                                    const float* __restrict__ Wsd) {
    const int i = blockIdx.x * 256 + threadIdx.x;
    const int k = i >> 7, c = i & 127;
    float v = 0.0f;
    if (c < 16)      v = Wb [k * HH + c];
    else if (c < 32) v = Wfd[k * HH + (c - 16)];
    else if (c < 48) v = Wsd[k * HH + (c - 32)];
    g_wcat[i] = __uint_as_float(f2tf32(v));
}

// ---------------- gate elementwise -------------------------------------------
__global__ __launch_bounds__(256) void gate_ew(const float* __restrict__ bfd,
                                               const float* __restrict__ bsd) {
    const int idx = blockIdx.x * 256 + threadIdx.x;
    const int bh = idx >> 12;
    const int l = idx & (LL - 1);
    const int b = bh >> 4, h = bh & 15;
    const float* row = g_gate + ((size_t)(b * LL + l)) * 128;
    g_beta[idx] = sigmoidf_(row[h]);
    g_lf[idx] = logf(sigmoidf_(row[16 + h] + bfd[h]) + 1e-6f);
    g_ls[idx] = logf(sigmoidf_(row[32 + h] + bsd[h]) + 1e-6f);
}

// ------- l2norm q,k ; k_beta ; v_scaled ; token-flux MLP -> alpha ------------
__global__ __launch_bounds__(256) void norm_kernel(const float* __restrict__ Wtf1,
                                                   const float* __restrict__ btf1,
                                                   const float* __restrict__ Wtf2,
                                                   const float* __restrict__ btf2) {
    const int w = threadIdx.x >> 5;
    const int lane = threadIdx.x & 31;
    const int gw = blockIdx.x * 8 + w;
    const int token = gw >> 4;
    const int h = gw & 15;
    const int b = token >> 12, l = token & (LL - 1);
    const size_t base = (size_t)token * DD + h * DKK;
    const int gidx = (b * HH + h) * LL + l;

    float q0 = g_q[base + lane], q1 = g_q[base + 32 + lane];
    float s = q0 * q0 + q1 * q1;
    #pragma unroll
    for (int off = 16; off > 0; off >>= 1) s += __shfl_xor_sync(0xffffffffu, s, off);
    const float rq = 1.0f / fmaxf(sqrtf(s), 1e-12f);

    float k0 = g_k[base + lane], k1 = g_k[base + 32 + lane];
    float s2 = k0 * k0 + k1 * k1;
    #pragma unroll
    for (int off = 16; off > 0; off >>= 1) s2 += __shfl_xor_sync(0xffffffffu, s2, off);
    const float rk = 1.0f / fmaxf(sqrtf(s2), 1e-12f);

    const float bet = g_beta[gidx];
    const float kb0 = k0 * rk * bet, kb1 = k1 * rk * bet;

    g_q[base + lane] = q0 * rq;
    g_q[base + 32 + lane] = q1 * rq;
    g_k[base + lane] = kb0;
    g_k[base + 32 + lane] = kb1;
    g_v[base + lane] *= bet;
    g_v[base + 32 + lane] *= bet;

    __shared__ float skb[8][64];
    skb[w][lane] = kb0;
    skb[w][lane + 32] = kb1;
    __syncwarp();

    float acc = btf1[lane];
    #pragma unroll 8
    for (int d = 0; d < 64; d++) acc += skb[w][d] * Wtf1[d * 32 + lane];
    acc = acc * sigmoidf_(acc);
    float p = acc * Wtf2[lane];
    #pragma unroll
    for (int off = 16; off > 0; off >>= 1) p += __shfl_xor_sync(0xffffffffu, p, off);
    if (lane == 0) {
        float t = sigmoidf_(p + btf2[0]);
        t = fminf(fmaxf(t, 0.01f), 0.99f);
        g_alpha[gidx] = 0.5f + 0.3f * t;
    }
}

// --------------- per-(b,h) log-cumsum scan -> decay weights ------------------
// single-pass: 16 elems/thread register scan + warp/block shuffle scan
__global__ __launch_bounds__(256) void scan_kernel() {
    const int bh = blockIdx.x;
    const int tid = threadIdx.x;
    const int lane = tid & 31, wid = tid >> 5;
    const float* lfp = g_lf + (size_t)bh * LL;
    const float* lsp = g_ls + (size_t)bh * LL;
    float* fwp = g_fw + (size_t)bh * LL;
    float* swp = g_sw + (size_t)bh * LL;

    float f[16], s[16];
    const int base = tid * 16;
    #pragma unroll
    for (int i = 0; i < 4; i++) {
        *(float4*)&f[i*4] = *(const float4*)&lfp[base + i*4];
        *(float4*)&s[i*4] = *(const float4*)&lsp[base + i*4];
    }
    #pragma unroll
    for (int i = 1; i < 16; i++) { f[i] += f[i-1]; s[i] += s[i-1]; }

    float incf = f[15], incs = s[15];
    #pragma unroll
    for (int off = 1; off < 32; off <<= 1) {
        float nf = __shfl_up_sync(0xffffffffu, incf, off);
        float ns = __shfl_up_sync(0xffffffffu, incs, off);
        if (lane >= off) { incf += nf; incs += ns; }
    }
    __shared__ float wfs[8], wss[8];
    __shared__ float totf_s, tots_s;
    if (lane == 31) { wfs[wid] = incf; wss[wid] = incs; }
    __syncthreads();
    if (tid == 0) {
        float af = 0.0f, as2 = 0.0f;
        #pragma unroll
        for (int i = 0; i < 8; i++) {
            float t1 = wfs[i], t2 = wss[i];
            wfs[i] = af; wss[i] = as2;
            af += t1; as2 += t2;
        }
        totf_s = af; tots_s = as2;
    }
    __syncthreads();
    const float offf = wfs[wid] + (incf - f[15]);
    const float offs = wss[wid] + (incs - s[15]);
    const float totf = totf_s, tots = tots_s;

    float sumf = 0.0f, sums = 0.0f;
    #pragma unroll
    for (int i = 0; i < 16; i++) {
        float wf = expf(totf - (offf + f[i]));
        float ws = expf(tots - (offs + s[i]));
        f[i] = wf; s[i] = ws;
        sumf += wf; sums += ws;
    }
    #pragma unroll
    for (int i = 0; i < 4; i++) {
        *(float4*)&fwp[base + i*4] = *(float4*)&f[i*4];
        *(float4*)&swp[base + i*4] = *(float4*)&s[i*4];
    }
    #pragma unroll
    for (int off = 16; off > 0; off >>= 1) {
        sumf += __shfl_xor_sync(0xffffffffu, sumf, off);
        sums += __shfl_xor_sync(0xffffffffu, sums, off);
    }
    __syncthreads();
    if (lane == 0) { wfs[wid] = sumf; wss[wid] = sums; }
    __syncthreads();
    if (tid == 0) {
        float a = 0.0f, b2 = 0.0f;
        #pragma unroll
        for (int i = 0; i < 8; i++) { a += wfs[i]; b2 += wss[i]; }
        g_rden[bh * 2 + 0] = 1.0f / (a + 1e-6f);
        g_rden[bh * 2 + 1] = 1.0f / (b2 + 1e-6f);
    }
}

// ---------------- zero the M accumulators ------------------------------------
__global__ void zeroM_kernel() {
    int i = blockIdx.x * blockDim.x + threadIdx.x;
    if (i < BH * 2 * DKK * DKK) g_M[i] = 0.0f;
}

// ---------------- M_fast / M_slow accumulation (KV outer products) -----------
#define MCHUNKS 8
__global__ __launch_bounds__(256) void mstate_kernel() {
    const int bh = blockIdx.y;
    const int chunk = blockIdx.x;
    const int b = bh / HH, h = bh % HH;
    const int l0 = chunk * (LL / MCHUNKS);
    const int tid = threadIdx.x;

    __shared__ __align__(16) float skb[16][64];
    __shared__ __align__(16) float sv[16][64];
    __shared__ float sfw[16], ssw[16];

    float accf[4][4], accs[4][4];
    #pragma unroll
    for (int i = 0; i < 4; i++)
        #pragma unroll
        for (int j = 0; j < 4; j++) { accf[i][j] = 0.0f; accs[i][j] = 0.0f; }

    const int tr = (tid / 16) * 4, tc = (tid % 16) * 4;
    const int r = (tid * 4) >> 6, cc = (tid * 4) & 63;

    for (int lc = 0; lc < LL / MCHUNKS; lc += 16) {
        const int l = l0 + lc + r;
        *(float4*)&skb[r][cc] = *(const float4*)&g_k[((size_t)b * LL + l) * DD + h * DKK + cc];
        *(float4*)&sv[r][cc]  = *(const float4*)&g_v[((size_t)b * LL + l) * DD + h * DKK + cc];
        if (tid < 16) {
            sfw[tid] = g_fw[(size_t)bh * LL + l0 + lc + tid];
            ssw[tid] = g_sw[(size_t)bh * LL + l0 + lc + tid];
        }
        __syncthreads();
        #pragma unroll
        for (int kk = 0; kk < 16; kk++) {
            const float wf = sfw[kk], ws = ssw[kk];
            float kf[4], ks2[4], vv[4];
            #pragma unroll
            for (int i = 0; i < 4; i++) {
                float kv = skb[kk][tr + i];
                kf[i] = kv * wf; ks2[i] = kv * ws;
            }
            #pragma unroll
            for (int j = 0; j < 4; j++) vv[j] = sv[kk][tc + j];
            #pragma unroll
            for (int i = 0; i < 4; i++)
                #pragma unroll
                for (int j = 0; j < 4; j++) {
                    accf[i][j] += kf[i] * vv[j];
                    accs[i][j] += ks2[i] * vv[j];
                }
        }
        __syncthreads();
    }
    float* Mf = g_M + (size_t)bh * 2 * DKK * DKK;
    float* Ms = Mf + DKK * DKK;
    #pragma unroll
    for (int i = 0; i < 4; i++)
        #pragma unroll
        for (int j = 0; j < 4; j++) {
            atomicAdd(&Mf[(tr + i) * DKK + tc + j], accf[i][j]);
            atomicAdd(&Ms[(tr + i) * DKK + tc + j], accs[i][j]);
        }
}

// ---------------- per-token output: alpha*q@Mf + (1-alpha)*q@Ms --------------
__global__ __launch_bounds__(256) void out_kernel() {
    const int bh = blockIdx.y;
    const int b = bh / HH, h = bh % HH;
    const int lbase = blockIdx.x * 128;
    const int tid = threadIdx.x;

    __shared__ __align__(16) float Mf[DKK * DKK];
    __shared__ __align__(16) float Ms[DKK * DKK];
    __shared__ float qb[256];

    const float rf = g_rden[bh * 2 + 0], rs = g_rden[bh * 2 + 1];
    const float* Mg = g_M + (size_t)bh * 2 * DKK * DKK;
    for (int i = tid; i < DKK * DKK; i += 256) {
        Mf[i] = Mg[i] * rf;
        Ms[i] = Mg[DKK * DKK + i] * rs;
    }
    __syncthreads();

    const int sub = tid >> 6, e = tid & 63;
    for (int t = 0; t < 32; t++) {
        const int l = lbase + t * 4 + sub;
        qb[tid] = g_q[((size_t)b * LL + l) * DD + h * DKK + e];
        __syncthreads();
        float sfv = 0.0f, ssv = 0.0f;
        #pragma unroll
        for (int d = 0; d < 64; d++) {
            const float qd = qb[sub * 64 + d];
            sfv += qd * Mf[d * 64 + e];
            ssv += qd * Ms[d * 64 + e];
        }
        const float a = g_alpha[(size_t)bh * LL + l];
        const float val = a * sfv + (1.0f - a) * ssv;
        // store tf32-rounded so the final GEMM's truncation is exact
        g_o[((size_t)b * LL + l) * DD + h * DKK + e] = __uint_as_float(f2tf32(val));
        __syncthreads();
    }
}

// -----------------------------------------------------------------------------
extern "C" void kernel_launch(void* const* d_in, const int* in_sizes, int n_in,
                              void* d_out, int out_size) {
    const float* x    = (const float*)d_in[0];
    const float* Wq   = (const float*)d_in[1];
    const float* Wk   = (const float*)d_in[2];
    const float* Wv   = (const float*)d_in[3];
    const float* Wb   = (const float*)d_in[4];
    const float* Wo   = (const float*)d_in[5];
    const float* Wfd  = (const float*)d_in[6];
    const float* bfd  = (const float*)d_in[7];
    const float* Wsd  = (const float*)d_in[8];
    const float* bsd  = (const float*)d_in[9];
    const float* Wtf1 = (const float*)d_in[10];
    const float* btf1 = (const float*)d_in[11];
    const float* Wtf2 = (const float*)d_in[12];
    const float* btf2 = (const float*)d_in[13];
    float* out = (float*)d_out;

    float *o_, *wcat_, *gate_, *xr_, *wr_;
    cudaGetSymbolAddress((void**)&o_, g_o);
    cudaGetSymbolAddress((void**)&wcat_, g_wcat);
    cudaGetSymbolAddress((void**)&gate_, g_gate);
    cudaGetSymbolAddress((void**)&xr_, g_xr);
    cudaGetSymbolAddress((void**)&wr_, g_wr);

    cudaFuncSetAttribute(gemm_qkv, cudaFuncAttributeMaxDynamicSharedMemorySize, GSMEM_BYTES);
    cudaFuncSetAttribute(gemm_one, cudaFuncAttributeMaxDynamicSharedMemorySize, GSMEM_BYTES);

    // 0) tf32 pre-rounding + gate weight pack
    round_x<<<(TOK * DD) / 1024, 256>>>(x);
    round_W<<<(4 * DD * DD) / 1024, 256>>>(Wq, Wk, Wv, Wo);
    packW_kernel<<<(DD * 128) / 256, 256>>>(Wb, Wfd, Wsd);

    // 1) big projections q,k,v (tensor cores, tf32, cp.async pipeline)
    gemm_qkv<<<dim3(DD / 128, TOK / 128, 3), 256, GSMEM_BYTES>>>();

    // 2) gate projections as one GEMM (N=128) + elementwise
    gemm_one<<<dim3(1, TOK / 128, 1), 256, GSMEM_BYTES>>>(xr_, wcat_, gate_, 128);
    gate_ew<<<(BH * LL) / 256, 256>>>(bfd, bsd);

    // 3) l2norm + k_beta + v_scaled + token-flux alpha
    norm_kernel<<<(TOK * HH) / 8, 256>>>(Wtf1, btf1, Wtf2, btf2);

    // 4) decay scan
    scan_kernel<<<BH, 256>>>();

    // 5) KV state accumulation
    zeroM_kernel<<<(BH * 2 * DKK * DKK + 255) / 256, 256>>>();
    mstate_kernel<<<dim3(MCHUNKS, BH), 256>>>();

    // 6) output blend (stores tf32-rounded o)
    out_kernel<<<dim3(LL / 128, BH), 256>>>();

    // 7) final projection
    gemm_one<<<dim3(DD / 128, TOK / 128, 1), 256, GSMEM_BYTES>>>(o_, wr_ + 3 * (size_t)DD * DD, out, DD);
}

// round 6
// speedup vs baseline: 2.7866x; 1.0251x over previous
#include <cuda_runtime.h>
#include <math.h>
#include <stdint.h>

// Problem constants
#define BB 2
#define LL 4096
#define DD 1024
#define HH 16
#define DKK 64
#define BH (BB*HH)          // 32
#define TOK (BB*LL)         // 8192

// ---------------- scratch (static device memory; no allocations) -------------
__device__ float g_xr[TOK*DD];    // tf32-rounded x
__device__ float g_wr[4*DD*DD];   // tf32-rounded Wq,Wk,Wv,Wo
__device__ float g_q[TOK*DD];
__device__ float g_k[TOK*DD];     // becomes k_beta
__device__ float g_v[TOK*DD];     // becomes v_scaled
__device__ float g_o[TOK*DD];     // stored tf32-rounded
__device__ float g_gate[TOK*128];
__device__ float g_wcat[DD*128];  // packed [Wb | Wfd | Wsd | 0], tf32-rounded
__device__ float g_beta[BH*LL];
__device__ float g_lf[BH*LL];
__device__ float g_ls[BH*LL];
__device__ float g_fw[BH*LL];
__device__ float g_sw[BH*LL];
__device__ float g_alpha[BH*LL];
__device__ float g_rden[BH*2];
__device__ float g_M[BH*2*DKK*DKK];

__device__ __forceinline__ float sigmoidf_(float x) { return 1.0f/(1.0f+expf(-x)); }
__device__ __forceinline__ uint32_t f2tf32(float x) {
    uint32_t r; asm("cvt.rna.tf32.f32 %0, %1;" : "=r"(r) : "f"(x)); return r;
}
__device__ __forceinline__ uint32_t smem_u32(const void* p) {
    uint32_t a;
    asm("{ .reg .u64 t; cvta.to.shared.u64 t, %1; cvt.u32.u64 %0, t; }" : "=r"(a) : "l"(p));
    return a;
}
__device__ __forceinline__ void cp_async16(uint32_t dst, const void* src) {
    asm volatile("cp.async.cg.shared.global [%0], [%1], 16;" :: "r"(dst), "l"(src));
}
#define CP_COMMIT() asm volatile("cp.async.commit_group;" ::: "memory")
#define CP_WAIT(n)  asm volatile("cp.async.wait_group %0;" :: "n"(n) : "memory")

// =========================== tf32 mma.sync GEMM ==============================
// C[M,N] = A[M,K=1024] * W[K=1024,N]; A,W pre-rounded to tf32 bit patterns.
// Tile 128x128, BK=16, 3-stage cp.async, 128 threads (4 warps), warp tile 64x64.
#define AST 20         // A smem row stride (floats)
#define BST 136        // B smem row stride (floats)
#define A_STG (128*AST)          // 2560 floats
#define B_STG (16*BST)           // 2176 floats
#define STG_FLOATS (A_STG + B_STG)  // 4736
#define GSTAGES 3
#define GSMEM_BYTES (GSTAGES*STG_FLOATS*4)   // 56832
#define NKITER (DD/16) // 64

__device__ __forceinline__ void mma8(float* c, const uint32_t* a, const uint32_t* b) {
    asm volatile(
        "mma.sync.aligned.m16n8k8.row.col.f32.tf32.tf32.f32 "
        "{%0,%1,%2,%3}, {%4,%5,%6,%7}, {%8,%9}, {%0,%1,%2,%3};"
        : "+f"(c[0]), "+f"(c[1]), "+f"(c[2]), "+f"(c[3])
        : "r"(a[0]), "r"(a[1]), "r"(a[2]), "r"(a[3]), "r"(b[0]), "r"(b[1]));
}

__device__ __forceinline__ void gemm_body(const float* __restrict__ A,
                                          const float* __restrict__ W,
                                          float* __restrict__ C, int N) {
    extern __shared__ float smp[];
    const uint32_t sbase = smem_u32(smp);

    const int tid = threadIdx.x;
    const int lane = tid & 31;
    const int wid = tid >> 5;            // 0..3
    const int g = lane >> 2, t4 = lane & 3;
    const int mbase = (wid & 1) * 64;
    const int nbase = (wid >> 1) * 64;
    const int crow = blockIdx.y * 128;
    const int ccol = blockIdx.x * 128;

    float acc[4][8][4];
    #pragma unroll
    for (int i = 0; i < 4; i++)
        #pragma unroll
        for (int j = 0; j < 8; j++)
            #pragma unroll
            for (int c = 0; c < 4; c++) acc[i][j][c] = 0.0f;

    // cp.async issue for one K-stage (128 threads: 4 A chunks + 4 B chunks each)
    auto issue = [&](int it) {
        const int k0 = it * 16;
        const uint32_t abase = sbase + (uint32_t)((it % GSTAGES) * STG_FLOATS) * 4u;
        const uint32_t bbase = abase + A_STG * 4u;
        #pragma unroll
        for (int j = 0; j < 4; j++) {
            const int ch = tid + 128 * j;           // 0..511
            const int ar = ch >> 2, ac = (ch & 3) * 4;
            cp_async16(abase + (uint32_t)(ar * AST + ac) * 4u,
                       &A[(size_t)(crow + ar) * DD + k0 + ac]);
        }
        #pragma unroll
        for (int j = 0; j < 4; j++) {
            const int ch = tid + 128 * j;
            const int br = ch >> 5, bc = (ch & 31) * 4;
            cp_async16(bbase + (uint32_t)(br * BST + bc) * 4u,
                       &W[(size_t)(k0 + br) * N + ccol + bc]);
        }
    };

    issue(0); CP_COMMIT();
    issue(1); CP_COMMIT();

    for (int it = 0; it < NKITER; it++) {
        CP_WAIT(1);
        __syncthreads();
        if (it + 2 < NKITER) issue(it + 2);
        CP_COMMIT();

        const float* as = smp + (it % GSTAGES) * STG_FLOATS;
        const float* bs = as + A_STG;
        #pragma unroll
        for (int ks = 0; ks < 2; ks++) {
            const int kk = ks * 8;
            uint32_t af[4][4];
            #pragma unroll
            for (int i = 0; i < 4; i++) {
                const int r0 = (mbase + i * 16 + g) * AST;
                af[i][0] = __float_as_uint(as[r0 + kk + t4]);
                af[i][1] = __float_as_uint(as[r0 + 8 * AST + kk + t4]);
                af[i][2] = __float_as_uint(as[r0 + kk + t4 + 4]);
                af[i][3] = __float_as_uint(as[r0 + 8 * AST + kk + t4 + 4]);
            }
            uint32_t bf[8][2];
            #pragma unroll
            for (int j = 0; j < 8; j++) {
                const int c0 = nbase + j * 8 + g;
                bf[j][0] = __float_as_uint(bs[(kk + t4) * BST + c0]);
                bf[j][1] = __float_as_uint(bs[(kk + t4 + 4) * BST + c0]);
            }
            #pragma unroll
            for (int i = 0; i < 4; i++)
                #pragma unroll
                for (int j = 0; j < 8; j++) mma8(acc[i][j], af[i], bf[j]);
        }
    }

    // ---- epilogue
    #pragma unroll
    for (int i = 0; i < 4; i++) {
        const int row = crow + mbase + i * 16 + g;
        #pragma unroll
        for (int j = 0; j < 8; j++) {
            const int col = ccol + nbase + j * 8 + t4 * 2;
            *(float2*)&C[(size_t)row * N + col] = make_float2(acc[i][j][0], acc[i][j][1]);
            *(float2*)&C[(size_t)(row + 8) * N + col] = make_float2(acc[i][j][2], acc[i][j][3]);
        }
    }
}

__global__ __launch_bounds__(128, 2) void gemm_qkv() {
    const float* W = g_wr + (size_t)blockIdx.z * DD * DD;
    float* C = (blockIdx.z == 0) ? g_q : (blockIdx.z == 1) ? g_k : g_v;
    gemm_body(g_xr, W, C, DD);
}

__global__ __launch_bounds__(128, 2) void gemm_one(const float* __restrict__ A,
                                                   const float* __restrict__ W,
                                                   float* __restrict__ C, int N) {
    gemm_body(A, W, C, N);
}

// ---------------- tf32 pre-rounding prepasses --------------------------------
__global__ __launch_bounds__(256) void round_x(const float* __restrict__ x) {
    const int i = (blockIdx.x * 256 + threadIdx.x) * 4;
    float4 v = *(const float4*)&x[i];
    uint4 u;
    u.x = f2tf32(v.x); u.y = f2tf32(v.y); u.z = f2tf32(v.z); u.w = f2tf32(v.w);
    *(uint4*)&g_xr[i] = u;
}

__global__ __launch_bounds__(256) void round_W(const float* __restrict__ Wq,
                                               const float* __restrict__ Wk,
                                               const float* __restrict__ Wv,
                                               const float* __restrict__ Wo) {
    const int i = (blockIdx.x * 256 + threadIdx.x) * 4;
    const int m = i / (DD * DD), off = i % (DD * DD);
    const float* src = (m == 0) ? Wq : (m == 1) ? Wk : (m == 2) ? Wv : Wo;
    float4 v = *(const float4*)&src[off];
    uint4 u;
    u.x = f2tf32(v.x); u.y = f2tf32(v.y); u.z = f2tf32(v.z); u.w = f2tf32(v.w);
    *(uint4*)&g_wr[i] = u;
}

// pack gate weights [Wb | Wfd | Wsd | 0] -> [K][128], tf32-rounded
__global__ __launch_bounds__(256) void packW_kernel(const float* __restrict__ Wb,
                                                    const float* __restrict__ Wfd,
                                                    const float* __restrict__ Wsd) {
    const int i = blockIdx.x * 256 + threadIdx.x;
    const int k = i >> 7, c = i & 127;
    float v = 0.0f;
    if (c < 16)      v = Wb [k * HH + c];
    else if (c < 32) v = Wfd[k * HH + (c - 16)];
    else if (c < 48) v = Wsd[k * HH + (c - 32)];
    g_wcat[i] = __uint_as_float(f2tf32(v));
}

// ---------------- gate elementwise -------------------------------------------
__global__ __launch_bounds__(256) void gate_ew(const float* __restrict__ bfd,
                                               const float* __restrict__ bsd) {
    const int idx = blockIdx.x * 256 + threadIdx.x;
    const int bh = idx >> 12;
    const int l = idx & (LL - 1);
    const int b = bh >> 4, h = bh & 15;
    const float* row = g_gate + ((size_t)(b * LL + l)) * 128;
    g_beta[idx] = sigmoidf_(row[h]);
    g_lf[idx] = logf(sigmoidf_(row[16 + h] + bfd[h]) + 1e-6f);
    g_ls[idx] = logf(sigmoidf_(row[32 + h] + bsd[h]) + 1e-6f);
}

// ------- l2norm q,k ; k_beta ; v_scaled ; token-flux MLP -> alpha ------------
__global__ __launch_bounds__(256) void norm_kernel(const float* __restrict__ Wtf1,
                                                   const float* __restrict__ btf1,
                                                   const float* __restrict__ Wtf2,
                                                   const float* __restrict__ btf2) {
    const int w = threadIdx.x >> 5;
    const int lane = threadIdx.x & 31;
    const int gw = blockIdx.x * 8 + w;
    const int token = gw >> 4;
    const int h = gw & 15;
    const int b = token >> 12, l = token & (LL - 1);
    const size_t base = (size_t)token * DD + h * DKK;
    const int gidx = (b * HH + h) * LL + l;

    float q0 = g_q[base + lane], q1 = g_q[base + 32 + lane];
    float s = q0 * q0 + q1 * q1;
    #pragma unroll
    for (int off = 16; off > 0; off >>= 1) s += __shfl_xor_sync(0xffffffffu, s, off);
    const float rq = 1.0f / fmaxf(sqrtf(s), 1e-12f);

    float k0 = g_k[base + lane], k1 = g_k[base + 32 + lane];
    float s2 = k0 * k0 + k1 * k1;
    #pragma unroll
    for (int off = 16; off > 0; off >>= 1) s2 += __shfl_xor_sync(0xffffffffu, s2, off);
    const float rk = 1.0f / fmaxf(sqrtf(s2), 1e-12f);

    const float bet = g_beta[gidx];
    const float kb0 = k0 * rk * bet, kb1 = k1 * rk * bet;

    g_q[base + lane] = q0 * rq;
    g_q[base + 32 + lane] = q1 * rq;
    g_k[base + lane] = kb0;
    g_k[base + 32 + lane] = kb1;
    g_v[base + lane] *= bet;
    g_v[base + 32 + lane] *= bet;

    __shared__ float skb[8][64];
    skb[w][lane] = kb0;
    skb[w][lane + 32] = kb1;
    __syncwarp();

    float acc = btf1[lane];
    #pragma unroll 8
    for (int d = 0; d < 64; d++) acc += skb[w][d] * Wtf1[d * 32 + lane];
    acc = acc * sigmoidf_(acc);
    float p = acc * Wtf2[lane];
    #pragma unroll
    for (int off = 16; off > 0; off >>= 1) p += __shfl_xor_sync(0xffffffffu, p, off);
    if (lane == 0) {
        float t = sigmoidf_(p + btf2[0]);
        t = fminf(fmaxf(t, 0.01f), 0.99f);
        g_alpha[gidx] = 0.5f + 0.3f * t;
    }
}

// --------------- per-(b,h) log-cumsum scan -> decay weights ------------------
__global__ __launch_bounds__(256) void scan_kernel() {
    const int bh = blockIdx.x;
    const int tid = threadIdx.x;
    const int lane = tid & 31, wid = tid >> 5;
    const float* lfp = g_lf + (size_t)bh * LL;
    const float* lsp = g_ls + (size_t)bh * LL;
    float* fwp = g_fw + (size_t)bh * LL;
    float* swp = g_sw + (size_t)bh * LL;

    float f[16], s[16];
    const int base = tid * 16;
    #pragma unroll
    for (int i = 0; i < 4; i++) {
        *(float4*)&f[i*4] = *(const float4*)&lfp[base + i*4];
        *(float4*)&s[i*4] = *(const float4*)&lsp[base + i*4];
    }
    #pragma unroll
    for (int i = 1; i < 16; i++) { f[i] += f[i-1]; s[i] += s[i-1]; }

    float incf = f[15], incs = s[15];
    #pragma unroll
    for (int off = 1; off < 32; off <<= 1) {
        float nf = __shfl_up_sync(0xffffffffu, incf, off);
        float ns = __shfl_up_sync(0xffffffffu, incs, off);
        if (lane >= off) { incf += nf; incs += ns; }
    }
    __shared__ float wfs[8], wss[8];
    __shared__ float totf_s, tots_s;
    if (lane == 31) { wfs[wid] = incf; wss[wid] = incs; }
    __syncthreads();
    if (tid == 0) {
        float af = 0.0f, as2 = 0.0f;
        #pragma unroll
        for (int i = 0; i < 8; i++) {
            float t1 = wfs[i], t2 = wss[i];
            wfs[i] = af; wss[i] = as2;
            af += t1; as2 += t2;
        }
        totf_s = af; tots_s = as2;
    }
    __syncthreads();
    const float offf = wfs[wid] + (incf - f[15]);
    const float offs = wss[wid] + (incs - s[15]);
    const float totf = totf_s, tots = tots_s;

    float sumf = 0.0f, sums = 0.0f;
    #pragma unroll
    for (int i = 0; i < 16; i++) {
        float wf = expf(totf - (offf + f[i]));
        float ws = expf(tots - (offs + s[i]));
        f[i] = wf; s[i] = ws;
        sumf += wf; sums += ws;
    }
    #pragma unroll
    for (int i = 0; i < 4; i++) {
        *(float4*)&fwp[base + i*4] = *(float4*)&f[i*4];
        *(float4*)&swp[base + i*4] = *(float4*)&s[i*4];
    }
    #pragma unroll
    for (int off = 16; off > 0; off >>= 1) {
        sumf += __shfl_xor_sync(0xffffffffu, sumf, off);
        sums += __shfl_xor_sync(0xffffffffu, sums, off);
    }
    __syncthreads();
    if (lane == 0) { wfs[wid] = sumf; wss[wid] = sums; }
    __syncthreads();
    if (tid == 0) {
        float a = 0.0f, b2 = 0.0f;
        #pragma unroll
        for (int i = 0; i < 8; i++) { a += wfs[i]; b2 += wss[i]; }
        g_rden[bh * 2 + 0] = 1.0f / (a + 1e-6f);
        g_rden[bh * 2 + 1] = 1.0f / (b2 + 1e-6f);
    }
}

// ---------------- zero the M accumulators ------------------------------------
__global__ void zeroM_kernel() {
    int i = blockIdx.x * blockDim.x + threadIdx.x;
    if (i < BH * 2 * DKK * DKK) g_M[i] = 0.0f;
}

// ---------------- M_fast / M_slow accumulation (KV outer products) -----------
#define MCHUNKS 8
__global__ __launch_bounds__(256) void mstate_kernel() {
    const int bh = blockIdx.y;
    const int chunk = blockIdx.x;
    const int b = bh / HH, h = bh % HH;
    const int l0 = chunk * (LL / MCHUNKS);
    const int tid = threadIdx.x;

    __shared__ __align__(16) float skb[16][64];
    __shared__ __align__(16) float sv[16][64];
    __shared__ float sfw[16], ssw[16];

    float accf[4][4], accs[4][4];
    #pragma unroll
    for (int i = 0; i < 4; i++)
        #pragma unroll
        for (int j = 0; j < 4; j++) { accf[i][j] = 0.0f; accs[i][j] = 0.0f; }

    const int tr = (tid / 16) * 4, tc = (tid % 16) * 4;
    const int r = (tid * 4) >> 6, cc = (tid * 4) & 63;

    for (int lc = 0; lc < LL / MCHUNKS; lc += 16) {
        const int l = l0 + lc + r;
        *(float4*)&skb[r][cc] = *(const float4*)&g_k[((size_t)b * LL + l) * DD + h * DKK + cc];
        *(float4*)&sv[r][cc]  = *(const float4*)&g_v[((size_t)b * LL + l) * DD + h * DKK + cc];
        if (tid < 16) {
            sfw[tid] = g_fw[(size_t)bh * LL + l0 + lc + tid];
            ssw[tid] = g_sw[(size_t)bh * LL + l0 + lc + tid];
        }
        __syncthreads();
        #pragma unroll
        for (int kk = 0; kk < 16; kk++) {
            const float wf = sfw[kk], ws = ssw[kk];
            float kf[4], ks2[4], vv[4];
            #pragma unroll
            for (int i = 0; i < 4; i++) {
                float kv = skb[kk][tr + i];
                kf[i] = kv * wf; ks2[i] = kv * ws;
            }
            #pragma unroll
            for (int j = 0; j < 4; j++) vv[j] = sv[kk][tc + j];
            #pragma unroll
            for (int i = 0; i < 4; i++)
                #pragma unroll
                for (int j = 0; j < 4; j++) {
                    accf[i][j] += kf[i] * vv[j];
                    accs[i][j] += ks2[i] * vv[j];
                }
        }
        __syncthreads();
    }
    float* Mf = g_M + (size_t)bh * 2 * DKK * DKK;
    float* Ms = Mf + DKK * DKK;
    #pragma unroll
    for (int i = 0; i < 4; i++)
        #pragma unroll
        for (int j = 0; j < 4; j++) {
            atomicAdd(&Mf[(tr + i) * DKK + tc + j], accf[i][j]);
            atomicAdd(&Ms[(tr + i) * DKK + tc + j], accs[i][j]);
        }
}

// ---------------- per-token output: alpha*q@Mf + (1-alpha)*q@Ms --------------
__global__ __launch_bounds__(256) void out_kernel() {
    const int bh = blockIdx.y;
    const int b = bh / HH, h = bh % HH;
    const int lbase = blockIdx.x * 128;
    const int tid = threadIdx.x;

    __shared__ __align__(16) float Mf[DKK * DKK];
    __shared__ __align__(16) float Ms[DKK * DKK];
    __shared__ float qb[256];

    const float rf = g_rden[bh * 2 + 0], rs = g_rden[bh * 2 + 1];
    const float* Mg = g_M + (size_t)bh * 2 * DKK * DKK;
    for (int i = tid; i < DKK * DKK; i += 256) {
        Mf[i] = Mg[i] * rf;
        Ms[i] = Mg[DKK * DKK + i] * rs;
    }
    __syncthreads();

    const int sub = tid >> 6, e = tid & 63;
    for (int t = 0; t < 32; t++) {
        const int l = lbase + t * 4 + sub;
        qb[tid] = g_q[((size_t)b * LL + l) * DD + h * DKK + e];
        __syncthreads();
        float sfv = 0.0f, ssv = 0.0f;
        #pragma unroll
        for (int d = 0; d < 64; d++) {
            const float qd = qb[sub * 64 + d];
            sfv += qd * Mf[d * 64 + e];
            ssv += qd * Ms[d * 64 + e];
        }
        const float a = g_alpha[(size_t)bh * LL + l];
        const float val = a * sfv + (1.0f - a) * ssv;
        g_o[((size_t)b * LL + l) * DD + h * DKK + e] = __uint_as_float(f2tf32(val));
        __syncthreads();
    }
}

// -----------------------------------------------------------------------------
extern "C" void kernel_launch(void* const* d_in, const int* in_sizes, int n_in,
                              void* d_out, int out_size) {
    const float* x    = (const float*)d_in[0];
    const float* Wq   = (const float*)d_in[1];
    const float* Wk   = (const float*)d_in[2];
    const float* Wv   = (const float*)d_in[3];
    const float* Wb   = (const float*)d_in[4];
    const float* Wo   = (const float*)d_in[5];
    const float* Wfd  = (const float*)d_in[6];
    const float* bfd  = (const float*)d_in[7];
    const float* Wsd  = (const float*)d_in[8];
    const float* bsd  = (const float*)d_in[9];
    const float* Wtf1 = (const float*)d_in[10];
    const float* btf1 = (const float*)d_in[11];
    const float* Wtf2 = (const float*)d_in[12];
    const float* btf2 = (const float*)d_in[13];
    float* out = (float*)d_out;

    float *o_, *wcat_, *gate_, *xr_, *wr_;
    cudaGetSymbolAddress((void**)&o_, g_o);
    cudaGetSymbolAddress((void**)&wcat_, g_wcat);
    cudaGetSymbolAddress((void**)&gate_, g_gate);
    cudaGetSymbolAddress((void**)&xr_, g_xr);
    cudaGetSymbolAddress((void**)&wr_, g_wr);

    cudaFuncSetAttribute(gemm_qkv, cudaFuncAttributeMaxDynamicSharedMemorySize, GSMEM_BYTES);
    cudaFuncSetAttribute(gemm_one, cudaFuncAttributeMaxDynamicSharedMemorySize, GSMEM_BYTES);

    // 0) tf32 pre-rounding + gate weight pack
    round_x<<<(TOK * DD) / 1024, 256>>>(x);
    round_W<<<(4 * DD * DD) / 1024, 256>>>(Wq, Wk, Wv, Wo);
    packW_kernel<<<(DD * 128) / 256, 256>>>(Wb, Wfd, Wsd);

    // 1) big projections q,k,v (tensor cores, tf32, cp.async pipeline)
    gemm_qkv<<<dim3(DD / 128, TOK / 128, 3), 128, GSMEM_BYTES>>>();

    // 2) gate projections as one GEMM (N=128) + elementwise
    gemm_one<<<dim3(1, TOK / 128, 1), 128, GSMEM_BYTES>>>(xr_, wcat_, gate_, 128);
    gate_ew<<<(BH * LL) / 256, 256>>>(bfd, bsd);

    // 3) l2norm + k_beta + v_scaled + token-flux alpha
    norm_kernel<<<(TOK * HH) / 8, 256>>>(Wtf1, btf1, Wtf2, btf2);

    // 4) decay scan
    scan_kernel<<<BH, 256>>>();

    // 5) KV state accumulation
    zeroM_kernel<<<(BH * 2 * DKK * DKK + 255) / 256, 256>>>();
    mstate_kernel<<<dim3(MCHUNKS, BH), 256>>>();

    // 6) output blend (stores tf32-rounded o)
    out_kernel<<<dim3(LL / 128, BH), 256>>>();

    // 7) final projection
    gemm_one<<<dim3(DD / 128, TOK / 128, 1), 128, GSMEM_BYTES>>>(o_, wr_ + 3 * (size_t)DD * DD, out, DD);
}

// round 7
// speedup vs baseline: 3.6968x; 1.3266x over previous
#include <cuda_runtime.h>
#include <cuda_fp16.h>
#include <math.h>
#include <stdint.h>

// Problem constants
#define BB 2
#define LL 4096
#define DD 1024
#define HH 16
#define DKK 64
#define BH (BB*HH)          // 32
#define TOK (BB*LL)         // 8192

// ---------------- scratch (static device memory; no allocations) -------------
__device__ __half g_xh[TOK*DD];     // fp16 x, row-major [m][k]
__device__ __half g_wh[4*DD*DD];    // fp16 W^T for q,k,v,o: [n][k]
__device__ __half g_oh[TOK*DD];     // fp16 o, row-major [m][k]
__device__ __half g_wch[128*DD];    // fp16 packed gate weights^T: [n=128][k]
__device__ float g_q[TOK*DD];
__device__ float g_k[TOK*DD];     // becomes k_beta
__device__ float g_v[TOK*DD];     // becomes v_scaled
__device__ float g_gate[TOK*128];
__device__ float g_beta[BH*LL];
__device__ float g_lf[BH*LL];
__device__ float g_ls[BH*LL];
__device__ float g_fw[BH*LL];
__device__ float g_sw[BH*LL];
__device__ float g_alpha[BH*LL];
__device__ float g_rden[BH*2];
__device__ float g_M[BH*2*DKK*DKK];

__device__ __forceinline__ float sigmoidf_(float x) { return 1.0f/(1.0f+expf(-x)); }
__device__ __forceinline__ uint32_t smem_u32(const void* p) {
    uint32_t a;
    asm("{ .reg .u64 t; cvta.to.shared.u64 t, %1; cvt.u32.u64 %0, t; }" : "=r"(a) : "l"(p));
    return a;
}
__device__ __forceinline__ void cp_async16(uint32_t dst, const void* src) {
    asm volatile("cp.async.cg.shared.global [%0], [%1], 16;" :: "r"(dst), "l"(src));
}
#define CP_COMMIT() asm volatile("cp.async.commit_group;" ::: "memory")
#define CP_WAIT(n)  asm volatile("cp.async.wait_group %0;" :: "n"(n) : "memory")

// =========================== fp16 mma.sync GEMM ==============================
// C[M,N] = A[M,K=1024] * Wt[N,K]^T ; A fp16 row-major [m][k], Wt fp16 [n][k].
// Tile 128x128, BK=32 halfs, 3-stage cp.async, 128 threads, warp tile 64x64.
#define ASTB 80                    // bytes per smem row (64B data + 16B pad)
#define A_STG_B (128*ASTB)         // 10240
#define B_STG_B (128*ASTB)         // 10240
#define STG_B (A_STG_B + B_STG_B)  // 20480
#define GSTAGES 3
#define GSMEM_BYTES (GSTAGES*STG_B)   // 61440
#define NKITER (DD/32) // 32

__device__ __forceinline__ void mma16(float* c, const uint32_t* a, const uint32_t* b) {
    asm volatile(
        "mma.sync.aligned.m16n8k16.row.col.f32.f16.f16.f32 "
        "{%0,%1,%2,%3}, {%4,%5,%6,%7}, {%8,%9}, {%0,%1,%2,%3};"
        : "+f"(c[0]), "+f"(c[1]), "+f"(c[2]), "+f"(c[3])
        : "r"(a[0]), "r"(a[1]), "r"(a[2]), "r"(a[3]), "r"(b[0]), "r"(b[1]));
}

__device__ __forceinline__ void gemm_body(const __half* __restrict__ A,
                                          const __half* __restrict__ Wt,
                                          float* __restrict__ C, int N) {
    extern __shared__ char smp[];
    const uint32_t sbase = smem_u32(smp);

    const int tid = threadIdx.x;
    const int lane = tid & 31;
    const int wid = tid >> 5;            // 0..3
    const int g = lane >> 2, t4 = lane & 3;
    const int mbase = (wid & 1) * 64;
    const int nbase = (wid >> 1) * 64;
    const int crow = blockIdx.y * 128;
    const int ccol = blockIdx.x * 128;

    float acc[4][8][4];
    #pragma unroll
    for (int i = 0; i < 4; i++)
        #pragma unroll
        for (int j = 0; j < 8; j++)
            #pragma unroll
            for (int c = 0; c < 4; c++) acc[i][j][c] = 0.0f;

    // cp.async one K-stage: A 512 16B-chunks + B 512 16B-chunks, 128 threads
    auto issue = [&](int it) {
        const int k0 = it * 32;
        const uint32_t abase = sbase + (uint32_t)((it % GSTAGES) * STG_B);
        const uint32_t bbase = abase + A_STG_B;
        #pragma unroll
        for (int j = 0; j < 4; j++) {
            const int ch = tid + 128 * j;           // 0..511
            const int r = ch >> 2, c16 = ch & 3;    // row, 16B unit (8 halfs)
            cp_async16(abase + (uint32_t)(r * ASTB + c16 * 16),
                       &A[(size_t)(crow + r) * DD + k0 + c16 * 8]);
        }
        #pragma unroll
        for (int j = 0; j < 4; j++) {
            const int ch = tid + 128 * j;
            const int r = ch >> 2, c16 = ch & 3;
            cp_async16(bbase + (uint32_t)(r * ASTB + c16 * 16),
                       &Wt[(size_t)(ccol + r) * DD + k0 + c16 * 8]);
        }
    };

    issue(0); CP_COMMIT();
    issue(1); CP_COMMIT();

    for (int it = 0; it < NKITER; it++) {
        CP_WAIT(1);
        __syncthreads();
        if (it + 2 < NKITER) issue(it + 2);
        CP_COMMIT();

        const char* as = smp + (it % GSTAGES) * STG_B;
        const char* bs = as + A_STG_B;
        #pragma unroll
        for (int ks = 0; ks < 2; ks++) {
            const int kb = ks * 32;   // byte offset of this k16 within the 64B row
            uint32_t af[4][4];
            #pragma unroll
            for (int i = 0; i < 4; i++) {
                const int r0 = (mbase + i * 16 + g) * ASTB;
                af[i][0] = *(const uint32_t*)(as + r0 + kb + 4 * t4);
                af[i][1] = *(const uint32_t*)(as + r0 + 8 * ASTB + kb + 4 * t4);
                af[i][2] = *(const uint32_t*)(as + r0 + kb + 16 + 4 * t4);
                af[i][3] = *(const uint32_t*)(as + r0 + 8 * ASTB + kb + 16 + 4 * t4);
            }
            uint32_t bf[8][2];
            #pragma unroll
            for (int j = 0; j < 8; j++) {
                const int rb = (nbase + j * 8 + g) * ASTB;
                bf[j][0] = *(const uint32_t*)(bs + rb + kb + 4 * t4);
                bf[j][1] = *(const uint32_t*)(bs + rb + kb + 16 + 4 * t4);
            }
            #pragma unroll
            for (int i = 0; i < 4; i++)
                #pragma unroll
                for (int j = 0; j < 8; j++) mma16(acc[i][j], af[i], bf[j]);
        }
    }

    // ---- epilogue
    #pragma unroll
    for (int i = 0; i < 4; i++) {
        const int row = crow + mbase + i * 16 + g;
        #pragma unroll
        for (int j = 0; j < 8; j++) {
            const int col = ccol + nbase + j * 8 + t4 * 2;
            *(float2*)&C[(size_t)row * N + col] = make_float2(acc[i][j][0], acc[i][j][1]);
            *(float2*)&C[(size_t)(row + 8) * N + col] = make_float2(acc[i][j][2], acc[i][j][3]);
        }
    }
}

__global__ __launch_bounds__(128, 2) void gemm_qkv() {
    const __half* Wt = g_wh + (size_t)blockIdx.z * DD * DD;
    float* C = (blockIdx.z == 0) ? g_q : (blockIdx.z == 1) ? g_k : g_v;
    gemm_body(g_xh, Wt, C, DD);
}

__global__ __launch_bounds__(128, 2) void gemm_one(const __half* __restrict__ A,
                                                   const __half* __restrict__ Wt,
                                                   float* __restrict__ C, int N) {
    gemm_body(A, Wt, C, N);
}

// ---------------- fp16 conversion prepasses ----------------------------------
// x -> fp16 (8 elems/thread, 16B stores)
__global__ __launch_bounds__(256) void half_x(const float* __restrict__ x) {
    const int i = (blockIdx.x * 256 + threadIdx.x) * 8;
    float4 v0 = *(const float4*)&x[i];
    float4 v1 = *(const float4*)&x[i + 4];
    __half2 h[4];
    h[0] = __floats2half2_rn(v0.x, v0.y);
    h[1] = __floats2half2_rn(v0.z, v0.w);
    h[2] = __floats2half2_rn(v1.x, v1.y);
    h[3] = __floats2half2_rn(v1.z, v1.w);
    *(uint4*)&g_xh[i] = *(uint4*)h;
}

// W (fp32 [k][n]) -> W^T fp16 [n][k], 4 matrices
__global__ __launch_bounds__(256) void transposeW(const float* __restrict__ W0,
                                                  const float* __restrict__ W1,
                                                  const float* __restrict__ W2,
                                                  const float* __restrict__ W3) {
    __shared__ float t[32][33];
    const float* W = (blockIdx.z == 0) ? W0 : (blockIdx.z == 1) ? W1 : (blockIdx.z == 2) ? W2 : W3;
    __half* out = g_wh + (size_t)blockIdx.z * DD * DD;
    const int tx = threadIdx.x, ty = threadIdx.y;
    const int xIn = blockIdx.x * 32 + tx;    // n
    const int yIn = blockIdx.y * 32 + ty;    // k
    #pragma unroll
    for (int j = 0; j < 32; j += 8) t[ty + j][tx] = W[(size_t)(yIn + j) * DD + xIn];
    __syncthreads();
    const int xOut = blockIdx.y * 32 + tx;   // k
    const int yOut = blockIdx.x * 32 + ty;   // n
    #pragma unroll
    for (int j = 0; j < 32; j += 8)
        out[(size_t)(yOut + j) * DD + xOut] = __float2half(t[tx][ty + j]);
}

// packed gate weights^T: out[c][k], c: 0-15 Wb, 16-31 Wfd, 32-47 Wsd, rest 0
__global__ __launch_bounds__(256) void packWT_kernel(const float* __restrict__ Wb,
                                                     const float* __restrict__ Wfd,
                                                     const float* __restrict__ Wsd) {
    const int i = blockIdx.x * 256 + threadIdx.x;   // over 128*DD
    const int c = i >> 10, k = i & (DD - 1);
    float v = 0.0f;
    if (c < 16)      v = Wb [k * HH + c];
    else if (c < 32) v = Wfd[k * HH + (c - 16)];
    else if (c < 48) v = Wsd[k * HH + (c - 32)];
    g_wch[i] = __float2half(v);
}

// ---------------- gate elementwise -------------------------------------------
__global__ __launch_bounds__(256) void gate_ew(const float* __restrict__ bfd,
                                               const float* __restrict__ bsd) {
    const int idx = blockIdx.x * 256 + threadIdx.x;
    const int bh = idx >> 12;
    const int l = idx & (LL - 1);
    const int b = bh >> 4, h = bh & 15;
    const float* row = g_gate + ((size_t)(b * LL + l)) * 128;
    g_beta[idx] = sigmoidf_(row[h]);
    g_lf[idx] = logf(sigmoidf_(row[16 + h] + bfd[h]) + 1e-6f);
    g_ls[idx] = logf(sigmoidf_(row[32 + h] + bsd[h]) + 1e-6f);
}

// ------- l2norm q,k ; k_beta ; v_scaled ; token-flux MLP -> alpha ------------
__global__ __launch_bounds__(256) void norm_kernel(const float* __restrict__ Wtf1,
                                                   const float* __restrict__ btf1,
                                                   const float* __restrict__ Wtf2,
                                                   const float* __restrict__ btf2) {
    const int w = threadIdx.x >> 5;
    const int lane = threadIdx.x & 31;
    const int gw = blockIdx.x * 8 + w;
    const int token = gw >> 4;
    const int h = gw & 15;
    const int b = token >> 12, l = token & (LL - 1);
    const size_t base = (size_t)token * DD + h * DKK;
    const int gidx = (b * HH + h) * LL + l;

    float q0 = g_q[base + lane], q1 = g_q[base + 32 + lane];
    float s = q0 * q0 + q1 * q1;
    #pragma unroll
    for (int off = 16; off > 0; off >>= 1) s += __shfl_xor_sync(0xffffffffu, s, off);
    const float rq = 1.0f / fmaxf(sqrtf(s), 1e-12f);

    float k0 = g_k[base + lane], k1 = g_k[base + 32 + lane];
    float s2 = k0 * k0 + k1 * k1;
    #pragma unroll
    for (int off = 16; off > 0; off >>= 1) s2 += __shfl_xor_sync(0xffffffffu, s2, off);
    const float rk = 1.0f / fmaxf(sqrtf(s2), 1e-12f);

    const float bet = g_beta[gidx];
    const float kb0 = k0 * rk * bet, kb1 = k1 * rk * bet;

    g_q[base + lane] = q0 * rq;
    g_q[base + 32 + lane] = q1 * rq;
    g_k[base + lane] = kb0;
    g_k[base + 32 + lane] = kb1;
    g_v[base + lane] *= bet;
    g_v[base + 32 + lane] *= bet;

    __shared__ float skb[8][64];
    skb[w][lane] = kb0;
    skb[w][lane + 32] = kb1;
    __syncwarp();

    float acc = btf1[lane];
    #pragma unroll 8
    for (int d = 0; d < 64; d++) acc += skb[w][d] * Wtf1[d * 32 + lane];
    acc = acc * sigmoidf_(acc);
    float p = acc * Wtf2[lane];
    #pragma unroll
    for (int off = 16; off > 0; off >>= 1) p += __shfl_xor_sync(0xffffffffu, p, off);
    if (lane == 0) {
        float t = sigmoidf_(p + btf2[0]);
        t = fminf(fmaxf(t, 0.01f), 0.99f);
        g_alpha[gidx] = 0.5f + 0.3f * t;
    }
}

// --------------- per-(b,h) log-cumsum scan -> decay weights ------------------
__global__ __launch_bounds__(256) void scan_kernel() {
    const int bh = blockIdx.x;
    const int tid = threadIdx.x;
    const int lane = tid & 31, wid = tid >> 5;
    const float* lfp = g_lf + (size_t)bh * LL;
    const float* lsp = g_ls + (size_t)bh * LL;
    float* fwp = g_fw + (size_t)bh * LL;
    float* swp = g_sw + (size_t)bh * LL;

    float f[16], s[16];
    const int base = tid * 16;
    #pragma unroll
    for (int i = 0; i < 4; i++) {
        *(float4*)&f[i*4] = *(const float4*)&lfp[base + i*4];
        *(float4*)&s[i*4] = *(const float4*)&lsp[base + i*4];
    }
    #pragma unroll
    for (int i = 1; i < 16; i++) { f[i] += f[i-1]; s[i] += s[i-1]; }

    float incf = f[15], incs = s[15];
    #pragma unroll
    for (int off = 1; off < 32; off <<= 1) {
        float nf = __shfl_up_sync(0xffffffffu, incf, off);
        float ns = __shfl_up_sync(0xffffffffu, incs, off);
        if (lane >= off) { incf += nf; incs += ns; }
    }
    __shared__ float wfs[8], wss[8];
    __shared__ float totf_s, tots_s;
    if (lane == 31) { wfs[wid] = incf; wss[wid] = incs; }
    __syncthreads();
    if (tid == 0) {
        float af = 0.0f, as2 = 0.0f;
        #pragma unroll
        for (int i = 0; i < 8; i++) {
            float t1 = wfs[i], t2 = wss[i];
            wfs[i] = af; wss[i] = as2;
            af += t1; as2 += t2;
        }
        totf_s = af; tots_s = as2;
    }
    __syncthreads();
    const float offf = wfs[wid] + (incf - f[15]);
    const float offs = wss[wid] + (incs - s[15]);
    const float totf = totf_s, tots = tots_s;

    float sumf = 0.0f, sums = 0.0f;
    #pragma unroll
    for (int i = 0; i < 16; i++) {
        float wf = expf(totf - (offf + f[i]));
        float ws = expf(tots - (offs + s[i]));
        f[i] = wf; s[i] = ws;
        sumf += wf; sums += ws;
    }
    #pragma unroll
    for (int i = 0; i < 4; i++) {
        *(float4*)&fwp[base + i*4] = *(float4*)&f[i*4];
        *(float4*)&swp[base + i*4] = *(float4*)&s[i*4];
    }
    #pragma unroll
    for (int off = 16; off > 0; off >>= 1) {
        sumf += __shfl_xor_sync(0xffffffffu, sumf, off);
        sums += __shfl_xor_sync(0xffffffffu, sums, off);
    }
    __syncthreads();
    if (lane == 0) { wfs[wid] = sumf; wss[wid] = sums; }
    __syncthreads();
    if (tid == 0) {
        float a = 0.0f, b2 = 0.0f;
        #pragma unroll
        for (int i = 0; i < 8; i++) { a += wfs[i]; b2 += wss[i]; }
        g_rden[bh * 2 + 0] = 1.0f / (a + 1e-6f);
        g_rden[bh * 2 + 1] = 1.0f / (b2 + 1e-6f);
    }
}

// ---------------- zero the M accumulators ------------------------------------
__global__ void zeroM_kernel() {
    int i = blockIdx.x * blockDim.x + threadIdx.x;
    if (i < BH * 2 * DKK * DKK) g_M[i] = 0.0f;
}

// ---------------- M_fast / M_slow accumulation (KV outer products) -----------
#define MCHUNKS 8
__global__ __launch_bounds__(256) void mstate_kernel() {
    const int bh = blockIdx.y;
    const int chunk = blockIdx.x;
    const int b = bh / HH, h = bh % HH;
    const int l0 = chunk * (LL / MCHUNKS);
    const int tid = threadIdx.x;

    __shared__ __align__(16) float skb[16][64];
    __shared__ __align__(16) float sv[16][64];
    __shared__ float sfw[16], ssw[16];

    float accf[4][4], accs[4][4];
    #pragma unroll
    for (int i = 0; i < 4; i++)
        #pragma unroll
        for (int j = 0; j < 4; j++) { accf[i][j] = 0.0f; accs[i][j] = 0.0f; }

    const int tr = (tid / 16) * 4, tc = (tid % 16) * 4;
    const int r = (tid * 4) >> 6, cc = (tid * 4) & 63;

    for (int lc = 0; lc < LL / MCHUNKS; lc += 16) {
        const int l = l0 + lc + r;
        *(float4*)&skb[r][cc] = *(const float4*)&g_k[((size_t)b * LL + l) * DD + h * DKK + cc];
        *(float4*)&sv[r][cc]  = *(const float4*)&g_v[((size_t)b * LL + l) * DD + h * DKK + cc];
        if (tid < 16) {
            sfw[tid] = g_fw[(size_t)bh * LL + l0 + lc + tid];
            ssw[tid] = g_sw[(size_t)bh * LL + l0 + lc + tid];
        }
        __syncthreads();
        #pragma unroll
        for (int kk = 0; kk < 16; kk++) {
            const float wf = sfw[kk], ws = ssw[kk];
            float kf[4], ks2[4], vv[4];
            #pragma unroll
            for (int i = 0; i < 4; i++) {
                float kv = skb[kk][tr + i];
                kf[i] = kv * wf; ks2[i] = kv * ws;
            }
            #pragma unroll
            for (int j = 0; j < 4; j++) vv[j] = sv[kk][tc + j];
            #pragma unroll
            for (int i = 0; i < 4; i++)
                #pragma unroll
                for (int j = 0; j < 4; j++) {
                    accf[i][j] += kf[i] * vv[j];
                    accs[i][j] += ks2[i] * vv[j];
                }
        }
        __syncthreads();
    }
    float* Mf = g_M + (size_t)bh * 2 * DKK * DKK;
    float* Ms = Mf + DKK * DKK;
    #pragma unroll
    for (int i = 0; i < 4; i++)
        #pragma unroll
        for (int j = 0; j < 4; j++) {
            atomicAdd(&Mf[(tr + i) * DKK + tc + j], accf[i][j]);
            atomicAdd(&Ms[(tr + i) * DKK + tc + j], accs[i][j]);
        }
}

// ---------------- per-token output: alpha*q@Mf + (1-alpha)*q@Ms --------------
__global__ __launch_bounds__(256) void out_kernel() {
    const int bh = blockIdx.y;
    const int b = bh / HH, h = bh % HH;
    const int lbase = blockIdx.x * 128;
    const int tid = threadIdx.x;

    __shared__ __align__(16) float Mf[DKK * DKK];
    __shared__ __align__(16) float Ms[DKK * DKK];
    __shared__ float qb[256];

    const float rf = g_rden[bh * 2 + 0], rs = g_rden[bh * 2 + 1];
    const float* Mg = g_M + (size_t)bh * 2 * DKK * DKK;
    for (int i = tid; i < DKK * DKK; i += 256) {
        Mf[i] = Mg[i] * rf;
        Ms[i] = Mg[DKK * DKK + i] * rs;
    }
    __syncthreads();

    const int sub = tid >> 6, e = tid & 63;
    for (int t = 0; t < 32; t++) {
        const int l = lbase + t * 4 + sub;
        qb[tid] = g_q[((size_t)b * LL + l) * DD + h * DKK + e];
        __syncthreads();
        float sfv = 0.0f, ssv = 0.0f;
        #pragma unroll
        for (int d = 0; d < 64; d++) {
            const float qd = qb[sub * 64 + d];
            sfv += qd * Mf[d * 64 + e];
            ssv += qd * Ms[d * 64 + e];
        }
        const float a = g_alpha[(size_t)bh * LL + l];
        const float val = a * sfv + (1.0f - a) * ssv;
        g_oh[((size_t)b * LL + l) * DD + h * DKK + e] = __float2half(val);
        __syncthreads();
    }
}

// -----------------------------------------------------------------------------
extern "C" void kernel_launch(void* const* d_in, const int* in_sizes, int n_in,
                              void* d_out, int out_size) {
    const float* x    = (const float*)d_in[0];
    const float* Wq   = (const float*)d_in[1];
    const float* Wk   = (const float*)d_in[2];
    const float* Wv   = (const float*)d_in[3];
    const float* Wb   = (const float*)d_in[4];
    const float* Wo   = (const float*)d_in[5];
    const float* Wfd  = (const float*)d_in[6];
    const float* bfd  = (const float*)d_in[7];
    const float* Wsd  = (const float*)d_in[8];
    const float* bsd  = (const float*)d_in[9];
    const float* Wtf1 = (const float*)d_in[10];
    const float* btf1 = (const float*)d_in[11];
    const float* Wtf2 = (const float*)d_in[12];
    const float* btf2 = (const float*)d_in[13];
    float* out = (float*)d_out;

    __half *oh_, *wch_, *xh_, *wh_;
    float *gate_;
    cudaGetSymbolAddress((void**)&oh_, g_oh);
    cudaGetSymbolAddress((void**)&wch_, g_wch);
    cudaGetSymbolAddress((void**)&gate_, g_gate);
    cudaGetSymbolAddress((void**)&xh_, g_xh);
    cudaGetSymbolAddress((void**)&wh_, g_wh);

    cudaFuncSetAttribute(gemm_qkv, cudaFuncAttributeMaxDynamicSharedMemorySize, GSMEM_BYTES);
    cudaFuncSetAttribute(gemm_one, cudaFuncAttributeMaxDynamicSharedMemorySize, GSMEM_BYTES);

    // 0) fp16 conversions: x, W^T (q,k,v,o), packed gate weights^T
    half_x<<<(TOK * DD) / 2048, 256>>>(x);
    transposeW<<<dim3(DD/32, DD/32, 4), dim3(32, 8)>>>(Wq, Wk, Wv, Wo);
    packWT_kernel<<<(128 * DD) / 256, 256>>>(Wb, Wfd, Wsd);

    // 1) big projections q,k,v (fp16 tensor cores)
    gemm_qkv<<<dim3(DD / 128, TOK / 128, 3), 128, GSMEM_BYTES>>>();

    // 2) gate projections as one GEMM (N=128) + elementwise
    gemm_one<<<dim3(1, TOK / 128, 1), 128, GSMEM_BYTES>>>(xh_, wch_, gate_, 128);
    gate_ew<<<(BH * LL) / 256, 256>>>(bfd, bsd);

    // 3) l2norm + k_beta + v_scaled + token-flux alpha
    norm_kernel<<<(TOK * HH) / 8, 256>>>(Wtf1, btf1, Wtf2, btf2);

    // 4) decay scan
    scan_kernel<<<BH, 256>>>();

    // 5) KV state accumulation
    zeroM_kernel<<<(BH * 2 * DKK * DKK + 255) / 256, 256>>>();
    mstate_kernel<<<dim3(MCHUNKS, BH), 256>>>();

    // 6) output blend (stores fp16 o)
    out_kernel<<<dim3(LL / 128, BH), 256>>>();

    // 7) final projection (fp16 tensor cores)
    gemm_one<<<dim3(DD / 128, TOK / 128, 1), 128, GSMEM_BYTES>>>(oh_, wh_ + 3 * (size_t)DD * DD, out, DD);
}

// round 9
// speedup vs baseline: 3.7425x; 1.0124x over previous
#include <cuda_runtime.h>
#include <cuda_fp16.h>
#include <math.h>
#include <stdint.h>

// Problem constants
#define BB 2
#define LL 4096
#define DD 1024
#define HH 16
#define DKK 64
#define BH (BB*HH)          // 32
#define TOK (BB*LL)         // 8192

// ---------------- scratch (static device memory; no allocations) -------------
__device__ __half g_xh[TOK*DD];     // fp16 x, row-major [m][k]
__device__ __half g_wh[4*DD*DD];    // fp16 W^T for q,k,v,o: [n][k]
__device__ __half g_oh[TOK*DD];     // fp16 o, row-major [token][d]
__device__ __half g_wch[128*DD];    // fp16 packed gate weights^T: [n=128][k]
__device__ __half g_qh[TOK*DD];     // per-head [bh][l][64]
__device__ __half g_kh[TOK*DD];     // per-head, becomes k_beta
__device__ __half g_vh[TOK*DD];     // per-head, becomes v_scaled
__device__ float g_gate[TOK*128];
__device__ float g_beta[BH*LL];
__device__ float g_lf[BH*LL];
__device__ float g_ls[BH*LL];
__device__ float g_fw[BH*LL];
__device__ float g_sw[BH*LL];
__device__ float g_alpha[BH*LL];
__device__ float g_rden[BH*2];
__device__ float g_M[BH*2*DKK*DKK];

__device__ __forceinline__ float sigmoidf_(float x) { return 1.0f/(1.0f+expf(-x)); }
__device__ __forceinline__ uint32_t smem_u32(const void* p) {
    uint32_t a;
    asm("{ .reg .u64 t; cvta.to.shared.u64 t, %1; cvt.u32.u64 %0, t; }" : "=r"(a) : "l"(p));
    return a;
}
__device__ __forceinline__ void cp_async16(uint32_t dst, const void* src) {
    asm volatile("cp.async.cg.shared.global [%0], [%1], 16;" :: "r"(dst), "l"(src));
}
#define CP_COMMIT() asm volatile("cp.async.commit_group;" ::: "memory")
#define CP_WAIT(n)  asm volatile("cp.async.wait_group %0;" :: "n"(n) : "memory")

__device__ __forceinline__ void mma16(float* c, const uint32_t* a, const uint32_t* b) {
    asm volatile(
        "mma.sync.aligned.m16n8k16.row.col.f32.f16.f16.f32 "
        "{%0,%1,%2,%3}, {%4,%5,%6,%7}, {%8,%9}, {%0,%1,%2,%3};"
        : "+f"(c[0]), "+f"(c[1]), "+f"(c[2]), "+f"(c[3])
        : "r"(a[0]), "r"(a[1]), "r"(a[2]), "r"(a[3]), "r"(b[0]), "r"(b[1]));
}
__device__ __forceinline__ void ldsm4(uint32_t& r0, uint32_t& r1, uint32_t& r2, uint32_t& r3, uint32_t addr) {
    asm volatile("ldmatrix.sync.aligned.m8n8.x4.shared.b16 {%0,%1,%2,%3}, [%4];"
        : "=r"(r0), "=r"(r1), "=r"(r2), "=r"(r3) : "r"(addr));
}
__device__ __forceinline__ void ldsm4t(uint32_t& r0, uint32_t& r1, uint32_t& r2, uint32_t& r3, uint32_t addr) {
    asm volatile("ldmatrix.sync.aligned.m8n8.x4.trans.shared.b16 {%0,%1,%2,%3}, [%4];"
        : "=r"(r0), "=r"(r1), "=r"(r2), "=r"(r3) : "r"(addr));
}

// =========================== fp16 mma.sync GEMM ==============================
// C[M,N] = A[M,K=1024] * Wt[N,K]^T. Tile 128x128, BK=32, 3-stage cp.async,
// 128 threads (4 warps), warp tile 64x64. OUTMODE 0: fp32 [m][N]; 1: fp16 per-head.
#define ASTB 80
#define A_STG_B (128*ASTB)
#define B_STG_B (128*ASTB)
#define STG_B (A_STG_B + B_STG_B)
#define GSTAGES 3
#define GSMEM_BYTES (GSTAGES*STG_B)   // 61440
#define NKITER (DD/32) // 32

template<int OUTMODE>
__device__ __forceinline__ void gemm_body(const __half* __restrict__ A,
                                          const __half* __restrict__ Wt,
                                          void* __restrict__ Cp, int N) {
    extern __shared__ char smp[];
    const uint32_t sbase = smem_u32(smp);

    const int tid = threadIdx.x;
    const int lane = tid & 31;
    const int wid = tid >> 5;
    const int g = lane >> 2, t4 = lane & 3;
    const int mbase = (wid & 1) * 64;
    const int nbase = (wid >> 1) * 64;
    const int crow = blockIdx.y * 128;
    const int ccol = blockIdx.x * 128;

    float acc[4][8][4];
    #pragma unroll
    for (int i = 0; i < 4; i++)
        #pragma unroll
        for (int j = 0; j < 8; j++)
            #pragma unroll
            for (int c = 0; c < 4; c++) acc[i][j][c] = 0.0f;

    auto issue = [&](int it) {
        const int k0 = it * 32;
        const uint32_t abase = sbase + (uint32_t)((it % GSTAGES) * STG_B);
        const uint32_t bbase = abase + A_STG_B;
        #pragma unroll
        for (int j = 0; j < 4; j++) {
            const int ch = tid + 128 * j;
            const int r = ch >> 2, c16 = ch & 3;
            cp_async16(abase + (uint32_t)(r * ASTB + c16 * 16),
                       &A[(size_t)(crow + r) * DD + k0 + c16 * 8]);
        }
        #pragma unroll
        for (int j = 0; j < 4; j++) {
            const int ch = tid + 128 * j;
            const int r = ch >> 2, c16 = ch & 3;
            cp_async16(bbase + (uint32_t)(r * ASTB + c16 * 16),
                       &Wt[(size_t)(ccol + r) * DD + k0 + c16 * 8]);
        }
    };

    issue(0); CP_COMMIT();
    issue(1); CP_COMMIT();

    for (int it = 0; it < NKITER; it++) {
        CP_WAIT(1);
        __syncthreads();
        if (it + 2 < NKITER) issue(it + 2);
        CP_COMMIT();

        const char* as = smp + (it % GSTAGES) * STG_B;
        const char* bs = as + A_STG_B;
        #pragma unroll
        for (int ks = 0; ks < 2; ks++) {
            const int kb = ks * 32;
            uint32_t af[4][4];
            #pragma unroll
            for (int i = 0; i < 4; i++) {
                const int r0 = (mbase + i * 16 + g) * ASTB;
                af[i][0] = *(const uint32_t*)(as + r0 + kb + 4 * t4);
                af[i][1] = *(const uint32_t*)(as + r0 + 8 * ASTB + kb + 4 * t4);
                af[i][2] = *(const uint32_t*)(as + r0 + kb + 16 + 4 * t4);
                af[i][3] = *(const uint32_t*)(as + r0 + 8 * ASTB + kb + 16 + 4 * t4);
            }
            uint32_t bf[8][2];
            #pragma unroll
            for (int j = 0; j < 8; j++) {
                const int rb = (nbase + j * 8 + g) * ASTB;
                bf[j][0] = *(const uint32_t*)(bs + rb + kb + 4 * t4);
                bf[j][1] = *(const uint32_t*)(bs + rb + kb + 16 + 4 * t4);
            }
            #pragma unroll
            for (int i = 0; i < 4; i++)
                #pragma unroll
                for (int j = 0; j < 8; j++) mma16(acc[i][j], af[i], bf[j]);
        }
    }

    if (OUTMODE == 0) {
        float* C = (float*)Cp;
        #pragma unroll
        for (int i = 0; i < 4; i++) {
            const int row = crow + mbase + i * 16 + g;
            #pragma unroll
            for (int j = 0; j < 8; j++) {
                const int col = ccol + nbase + j * 8 + t4 * 2;
                *(float2*)&C[(size_t)row * N + col] = make_float2(acc[i][j][0], acc[i][j][1]);
                *(float2*)&C[(size_t)(row + 8) * N + col] = make_float2(acc[i][j][2], acc[i][j][3]);
            }
        }
    } else {
        __half* C = (__half*)Cp;
        #pragma unroll
        for (int i = 0; i < 4; i++) {
            const int row = crow + mbase + i * 16 + g;
            const int b = row >> 12, l = row & (LL - 1);
            #pragma unroll
            for (int j = 0; j < 8; j++) {
                const int col = ccol + nbase + j * 8 + t4 * 2;
                const int h = col >> 6, d = col & 63;
                const size_t o0 = ((size_t)(b * HH + h) * LL + l) * 64 + d;
                const size_t o1 = ((size_t)(b * HH + h) * LL + (l + 8)) * 64 + d;
                *(__half2*)&C[o0] = __floats2half2_rn(acc[i][j][0], acc[i][j][1]);
                *(__half2*)&C[o1] = __floats2half2_rn(acc[i][j][2], acc[i][j][3]);
            }
        }
    }
}

__global__ __launch_bounds__(128, 2) void gemm_qkv() {
    const __half* Wt = g_wh + (size_t)blockIdx.z * DD * DD;
    __half* C = (blockIdx.z == 0) ? g_qh : (blockIdx.z == 1) ? g_kh : g_vh;
    gemm_body<1>(g_xh, Wt, C, DD);
}

__global__ __launch_bounds__(128, 2) void gemm_one(const __half* __restrict__ A,
                                                   const __half* __restrict__ Wt,
                                                   float* __restrict__ C, int N) {
    gemm_body<0>(A, Wt, C, N);
}

// ---------------- fp16 conversion prepasses ----------------------------------
__global__ __launch_bounds__(256) void half_x(const float* __restrict__ x) {
    const int i = (blockIdx.x * 256 + threadIdx.x) * 8;
    float4 v0 = *(const float4*)&x[i];
    float4 v1 = *(const float4*)&x[i + 4];
    __half2 h[4];
    h[0] = __floats2half2_rn(v0.x, v0.y);
    h[1] = __floats2half2_rn(v0.z, v0.w);
    h[2] = __floats2half2_rn(v1.x, v1.y);
    h[3] = __floats2half2_rn(v1.z, v1.w);
    *(uint4*)&g_xh[i] = *(uint4*)h;
}

__global__ __launch_bounds__(256) void transposeW(const float* __restrict__ W0,
                                                  const float* __restrict__ W1,
                                                  const float* __restrict__ W2,
                                                  const float* __restrict__ W3) {
    __shared__ float t[32][33];
    const float* W = (blockIdx.z == 0) ? W0 : (blockIdx.z == 1) ? W1 : (blockIdx.z == 2) ? W2 : W3;
    __half* out = g_wh + (size_t)blockIdx.z * DD * DD;
    const int tx = threadIdx.x, ty = threadIdx.y;
    const int xIn = blockIdx.x * 32 + tx;
    const int yIn = blockIdx.y * 32 + ty;
    #pragma unroll
    for (int j = 0; j < 32; j += 8) t[ty + j][tx] = W[(size_t)(yIn + j) * DD + xIn];
    __syncthreads();
    const int xOut = blockIdx.y * 32 + tx;
    const int yOut = blockIdx.x * 32 + ty;
    #pragma unroll
    for (int j = 0; j < 32; j += 8)
        out[(size_t)(yOut + j) * DD + xOut] = __float2half(t[tx][ty + j]);
}

__global__ __launch_bounds__(256) void packWT_kernel(const float* __restrict__ Wb,
                                                     const float* __restrict__ Wfd,
                                                     const float* __restrict__ Wsd) {
    const int i = blockIdx.x * 256 + threadIdx.x;
    const int c = i >> 10, k = i & (DD - 1);
    float v = 0.0f;
    if (c < 16)      v = Wb [k * HH + c];
    else if (c < 32) v = Wfd[k * HH + (c - 16)];
    else if (c < 48) v = Wsd[k * HH + (c - 32)];
    g_wch[i] = __float2half(v);
}

// ---------------- gate elementwise -------------------------------------------
__global__ __launch_bounds__(256) void gate_ew(const float* __restrict__ bfd,
                                               const float* __restrict__ bsd) {
    const int idx = blockIdx.x * 256 + threadIdx.x;
    const int bh = idx >> 12;
    const int l = idx & (LL - 1);
    const int b = bh >> 4, h = bh & 15;
    const float* row = g_gate + ((size_t)(b * LL + l)) * 128;
    g_beta[idx] = sigmoidf_(row[h]);
    g_lf[idx] = logf(sigmoidf_(row[16 + h] + bfd[h]) + 1e-6f);
    g_ls[idx] = logf(sigmoidf_(row[32 + h] + bsd[h]) + 1e-6f);
}

// ------- l2norm q,k ; k_beta ; v_scaled ; token-flux MLP -> alpha ------------
// warp per (bh,l); fp16 in-place on per-head arrays
__global__ __launch_bounds__(256) void norm_kernel(const float* __restrict__ Wtf1,
                                                   const float* __restrict__ btf1,
                                                   const float* __restrict__ Wtf2,
                                                   const float* __restrict__ btf2) {
    const int w = threadIdx.x >> 5;
    const int lane = threadIdx.x & 31;
    const int gw = blockIdx.x * 8 + w;      // bh*LL + l
    const size_t base = (size_t)gw * 64;

    float2 q = __half22float2(*(__half2*)&g_qh[base + 2 * lane]);
    float s = q.x * q.x + q.y * q.y;
    #pragma unroll
    for (int off = 16; off > 0; off >>= 1) s += __shfl_xor_sync(0xffffffffu, s, off);
    const float rq = 1.0f / fmaxf(sqrtf(s), 1e-12f);

    float2 k = __half22float2(*(__half2*)&g_kh[base + 2 * lane]);
    float s2 = k.x * k.x + k.y * k.y;
    #pragma unroll
    for (int off = 16; off > 0; off >>= 1) s2 += __shfl_xor_sync(0xffffffffu, s2, off);
    const float rk = 1.0f / fmaxf(sqrtf(s2), 1e-12f);

    const float bet = g_beta[gw];
    const float kb0 = k.x * rk * bet, kb1 = k.y * rk * bet;

    *(__half2*)&g_qh[base + 2 * lane] = __floats2half2_rn(q.x * rq, q.y * rq);
    *(__half2*)&g_kh[base + 2 * lane] = __floats2half2_rn(kb0, kb1);
    float2 v = __half22float2(*(__half2*)&g_vh[base + 2 * lane]);
    *(__half2*)&g_vh[base + 2 * lane] = __floats2half2_rn(v.x * bet, v.y * bet);

    __shared__ float skb[8][64];
    skb[w][2 * lane] = kb0;
    skb[w][2 * lane + 1] = kb1;
    __syncwarp();

    float acc = btf1[lane];
    #pragma unroll 8
    for (int d = 0; d < 64; d++) acc += skb[w][d] * Wtf1[d * 32 + lane];
    acc = acc * sigmoidf_(acc);
    float p = acc * Wtf2[lane];
    #pragma unroll
    for (int off = 16; off > 0; off >>= 1) p += __shfl_xor_sync(0xffffffffu, p, off);
    if (lane == 0) {
        float t = sigmoidf_(p + btf2[0]);
        t = fminf(fmaxf(t, 0.01f), 0.99f);
        g_alpha[gw] = 0.5f + 0.3f * t;
    }
}

// --------------- per-(b,h) log-cumsum scan -> decay weights ------------------
__global__ __launch_bounds__(256) void scan_kernel() {
    const int bh = blockIdx.x;
    const int tid = threadIdx.x;
    const int lane = tid & 31, wid = tid >> 5;
    const float* lfp = g_lf + (size_t)bh * LL;
    const float* lsp = g_ls + (size_t)bh * LL;
    float* fwp = g_fw + (size_t)bh * LL;
    float* swp = g_sw + (size_t)bh * LL;

    float f[16], s[16];
    const int base = tid * 16;
    #pragma unroll
    for (int i = 0; i < 4; i++) {
        *(float4*)&f[i*4] = *(const float4*)&lfp[base + i*4];
        *(float4*)&s[i*4] = *(const float4*)&lsp[base + i*4];
    }
    #pragma unroll
    for (int i = 1; i < 16; i++) { f[i] += f[i-1]; s[i] += s[i-1]; }

    float incf = f[15], incs = s[15];
    #pragma unroll
    for (int off = 1; off < 32; off <<= 1) {
        float nf = __shfl_up_sync(0xffffffffu, incf, off);
        float ns = __shfl_up_sync(0xffffffffu, incs, off);
        if (lane >= off) { incf += nf; incs += ns; }
    }
    __shared__ float wfs[8], wss[8];
    __shared__ float totf_s, tots_s;
    if (lane == 31) { wfs[wid] = incf; wss[wid] = incs; }
    __syncthreads();
    if (tid == 0) {
        float af = 0.0f, as2 = 0.0f;
        #pragma unroll
        for (int i = 0; i < 8; i++) {
            float t1 = wfs[i], t2 = wss[i];
            wfs[i] = af; wss[i] = as2;
            af += t1; as2 += t2;
        }
        totf_s = af; tots_s = as2;
    }
    __syncthreads();
    const float offf = wfs[wid] + (incf - f[15]);
    const float offs = wss[wid] + (incs - s[15]);
    const float totf = totf_s, tots = tots_s;

    float sumf = 0.0f, sums = 0.0f;
    #pragma unroll
    for (int i = 0; i < 16; i++) {
        float wf = expf(totf - (offf + f[i]));
        float ws = expf(tots - (offs + s[i]));
        f[i] = wf; s[i] = ws;
        sumf += wf; sums += ws;
    }
    #pragma unroll
    for (int i = 0; i < 4; i++) {
        *(float4*)&fwp[base + i*4] = *(float4*)&f[i*4];
        *(float4*)&swp[base + i*4] = *(float4*)&s[i*4];
    }
    #pragma unroll
    for (int off = 16; off > 0; off >>= 1) {
        sumf += __shfl_xor_sync(0xffffffffu, sumf, off);
        sums += __shfl_xor_sync(0xffffffffu, sums, off);
    }
    __syncthreads();
    if (lane == 0) { wfs[wid] = sumf; wss[wid] = sums; }
    __syncthreads();
    if (tid == 0) {
        float a = 0.0f, b2 = 0.0f;
        #pragma unroll
        for (int i = 0; i < 8; i++) { a += wfs[i]; b2 += wss[i]; }
        g_rden[bh * 2 + 0] = 1.0f / (a + 1e-6f);
        g_rden[bh * 2 + 1] = 1.0f / (b2 + 1e-6f);
    }
}

// ---------------- zero the M accumulators ------------------------------------
__global__ void zeroM_kernel() {
    int i = blockIdx.x * blockDim.x + threadIdx.x;
    if (i < BH * 2 * DKK * DKK) g_M[i] = 0.0f;
}

// ---------------- M states via fp16 tensor cores -----------------------------
// C[128,64] per (bh): rows 0-63 = Mf, 64-127 = Ms. A = [kw_f | kw_s] (stacked),
// B = v. Each CTA handles one l-chunk, atomicAdd into g_M.
#define NCH 16
__global__ __launch_bounds__(128) void mstate_kernel() {
    const int bh = blockIdx.y;
    const int chunk = blockIdx.x;
    const int l0 = chunk * (LL / NCH);      // 256-l chunk
    const int tid = threadIdx.x;
    const int lane = tid & 31, wid = tid >> 5;
    const int g = lane >> 2, t4 = lane & 3;
    const int s = wid >> 1;                  // state (0 fast, 1 slow)
    const int mh = (wid & 1) * 32;           // d-half within state

    __shared__ __half skw[2][32][72];
    __shared__ __half sv[32][72];

    float acc[2][8][4];
    #pragma unroll
    for (int i = 0; i < 2; i++)
        #pragma unroll
        for (int j = 0; j < 8; j++)
            #pragma unroll
            for (int c = 0; c < 4; c++) acc[i][j][c] = 0.0f;

    for (int lt = 0; lt < LL / NCH; lt += 32) {
        #pragma unroll
        for (int c = 0; c < 2; c++) {
            const int ch = tid + 128 * c;       // 0..255
            const int r = ch >> 3, d0 = (ch & 7) * 8;
            const int l = l0 + lt + r;
            const size_t gbase = ((size_t)bh * LL + l) * 64 + d0;
            uint4 kk = *(const uint4*)&g_kh[gbase];
            const float wf = g_fw[bh * LL + l], ws = g_sw[bh * LL + l];
            __half2* hp = (__half2*)&kk;
            uint4 of, os;
            __half2* ofp = (__half2*)&of;
            __half2* osp = (__half2*)&os;
            #pragma unroll
            for (int i = 0; i < 4; i++) {
                float2 fv = __half22float2(hp[i]);
                ofp[i] = __floats2half2_rn(fv.x * wf, fv.y * wf);
                osp[i] = __floats2half2_rn(fv.x * ws, fv.y * ws);
            }
            *(uint4*)&skw[0][r][d0] = of;
            *(uint4*)&skw[1][r][d0] = os;
            *(uint4*)&sv[r][d0] = *(const uint4*)&g_vh[gbase];
        }
        __syncthreads();

        #pragma unroll
        for (int ks = 0; ks < 2; ks++) {
            const int l0k = ks * 16;
            uint32_t af[2][4];
            #pragma unroll
            for (int i = 0; i < 2; i++) {
                const int m0 = mh + 16 * i;
                const int row = l0k + (lane & 7) + ((lane >> 4) << 3);
                const int col = m0 + (((lane >> 3) & 1) << 3);
                ldsm4t(af[i][0], af[i][1], af[i][2], af[i][3], smem_u32(&skw[s][row][col]));
            }
            uint32_t bf[8][2];
            #pragma unroll
            for (int jj = 0; jj < 4; jj++) {
                const int row = l0k + (lane & 7) + (((lane >> 3) & 1) << 3);
                const int col = 16 * jj + ((lane >> 4) << 3);
                ldsm4t(bf[2*jj][0], bf[2*jj][1], bf[2*jj+1][0], bf[2*jj+1][1],
                       smem_u32(&sv[row][col]));
            }
            #pragma unroll
            for (int i = 0; i < 2; i++)
                #pragma unroll
                for (int j = 0; j < 8; j++) mma16(acc[i][j], af[i], bf[j]);
        }
        __syncthreads();
    }

    float* M = g_M + ((size_t)bh * 2 + s) * DKK * DKK;
    #pragma unroll
    for (int i = 0; i < 2; i++) {
        const int d = mh + 16 * i + g;
        #pragma unroll
        for (int j = 0; j < 8; j++) {
            const int e = 8 * j + 2 * t4;
            atomicAdd(&M[d * 64 + e],       acc[i][j][0]);
            atomicAdd(&M[d * 64 + e + 1],   acc[i][j][1]);
            atomicAdd(&M[(d + 8) * 64 + e],     acc[i][j][2]);
            atomicAdd(&M[(d + 8) * 64 + e + 1], acc[i][j][3]);
        }
    }
}

// ---------------- output: alpha*q@Mf + (1-alpha)*q@Ms, fp16 tensor cores -----
// CTA per (bh, 128-l block). B = [Mf | Ms] (64x128) hoisted into registers.
__global__ __launch_bounds__(128) void out_kernel() {
    const int bh = blockIdx.y;
    const int lb = blockIdx.x * 128;
    const int b = bh >> 4, h = bh & 15;
    const int tid = threadIdx.x;
    const int lane = tid & 31, w = tid >> 5;
    const int g = lane >> 2, t4 = lane & 3;

    __shared__ __half Mh[64][136];
    __shared__ __half sq[32][72];
    __shared__ float sal[32];

    const float rf = g_rden[bh * 2 + 0], rs = g_rden[bh * 2 + 1];
    const float* Mg = g_M + (size_t)bh * 2 * DKK * DKK;
    for (int i = tid; i < 64 * 128; i += 128) {
        const int d = i >> 7, e2 = i & 127;
        const float sc = (e2 < 64) ? rf : rs;
        Mh[d][e2] = __float2half(Mg[(e2 < 64 ? 0 : DKK*DKK - 64) + d * 64 + e2] * sc);
    }
    __syncthreads();

    // hoist B frags: warp w: fast cols 16w..16w+15 (tiles j=0,1), slow same e (j=2,3)
    uint32_t bf[4][4][2];
    #pragma unroll
    for (int kt = 0; kt < 4; kt++) {
        const int k0 = 16 * kt;
        const int row = k0 + (lane & 7) + (((lane >> 3) & 1) << 3);
        {
            const int col = 16 * w + ((lane >> 4) << 3);
            ldsm4t(bf[kt][0][0], bf[kt][0][1], bf[kt][1][0], bf[kt][1][1],
                   smem_u32(&Mh[row][col]));
        }
        {
            const int col = 64 + 16 * w + ((lane >> 4) << 3);
            ldsm4t(bf[kt][2][0], bf[kt][2][1], bf[kt][3][0], bf[kt][3][1],
                   smem_u32(&Mh[row][col]));
        }
    }

    for (int lt = 0; lt < 4; lt++) {
        #pragma unroll
        for (int c = 0; c < 2; c++) {
            const int ch = tid + 128 * c;
            const int r = ch >> 3, d0 = (ch & 7) * 8;
            *(uint4*)&sq[r][d0] =
                *(const uint4*)&g_qh[((size_t)bh * LL + lb + lt * 32 + r) * 64 + d0];
        }
        if (tid < 32) sal[tid] = g_alpha[bh * LL + lb + lt * 32 + tid];
        __syncthreads();

        float acc[2][4][4];
        #pragma unroll
        for (int i = 0; i < 2; i++)
            #pragma unroll
            for (int j = 0; j < 4; j++)
                #pragma unroll
                for (int c = 0; c < 4; c++) acc[i][j][c] = 0.0f;

        #pragma unroll
        for (int kt = 0; kt < 4; kt++) {
            const int k0 = 16 * kt;
            uint32_t af[2][4];
            #pragma unroll
            for (int i = 0; i < 2; i++) {
                const int row = 16 * i + (lane & 15);
                const int col = k0 + ((lane >> 4) << 3);
                ldsm4(af[i][0], af[i][1], af[i][2], af[i][3], smem_u32(&sq[row][col]));
            }
            #pragma unroll
            for (int i = 0; i < 2; i++)
                #pragma unroll
                for (int j = 0; j < 4; j++) mma16(acc[i][j], af[i], bf[kt][j]);
        }

        // blend + write
        #pragma unroll
        for (int i = 0; i < 2; i++) {
            const int r0 = 16 * i + g, r1 = r0 + 8;
            const float a0 = sal[r0], a1 = sal[r1];
            #pragma unroll
            for (int j = 0; j < 2; j++) {
                const int e = 16 * w + 8 * j + 2 * t4;
                const float o00 = a0 * acc[i][j][0] + (1.0f - a0) * acc[i][j+2][0];
                const float o01 = a0 * acc[i][j][1] + (1.0f - a0) * acc[i][j+2][1];
                const float o10 = a1 * acc[i][j][2] + (1.0f - a1) * acc[i][j+2][2];
                const float o11 = a1 * acc[i][j][3] + (1.0f - a1) * acc[i][j+2][3];
                const int l0r = lb + lt * 32 + r0;
                const int l1r = lb + lt * 32 + r1;
                *(__half2*)&g_oh[((size_t)(b * LL) + l0r) * DD + h * 64 + e] =
                    __floats2half2_rn(o00, o01);
                *(__half2*)&g_oh[((size_t)(b * LL) + l1r) * DD + h * 64 + e] =
                    __floats2half2_rn(o10, o11);
            }
        }
        __syncthreads();
    }
}

// -----------------------------------------------------------------------------
extern "C" void kernel_launch(void* const* d_in, const int* in_sizes, int n_in,
                              void* d_out, int out_size) {
    const float* x    = (const float*)d_in[0];
    const float* Wq   = (const float*)d_in[1];
    const float* Wk   = (const float*)d_in[2];
    const float* Wv   = (const float*)d_in[3];
    const float* Wb   = (const float*)d_in[4];
    const float* Wo   = (const float*)d_in[5];
    const float* Wfd  = (const float*)d_in[6];
    const float* bfd  = (const float*)d_in[7];
    const float* Wsd  = (const float*)d_in[8];
    const float* bsd  = (const float*)d_in[9];
    const float* Wtf1 = (const float*)d_in[10];
    const float* btf1 = (const float*)d_in[11];
    const float* Wtf2 = (const float*)d_in[12];
    const float* btf2 = (const float*)d_in[13];
    float* out = (float*)d_out;

    __half *oh_, *wch_, *xh_, *wh_;
    float *gate_;
    cudaGetSymbolAddress((void**)&oh_, g_oh);
    cudaGetSymbolAddress((void**)&wch_, g_wch);
    cudaGetSymbolAddress((void**)&gate_, g_gate);
    cudaGetSymbolAddress((void**)&xh_, g_xh);
    cudaGetSymbolAddress((void**)&wh_, g_wh);

    cudaFuncSetAttribute(gemm_qkv, cudaFuncAttributeMaxDynamicSharedMemorySize, GSMEM_BYTES);
    cudaFuncSetAttribute(gemm_one, cudaFuncAttributeMaxDynamicSharedMemorySize, GSMEM_BYTES);

    // 0) fp16 conversions
    half_x<<<(TOK * DD) / 2048, 256>>>(x);
    transposeW<<<dim3(DD/32, DD/32, 4), dim3(32, 8)>>>(Wq, Wk, Wv, Wo);
    packWT_kernel<<<(128 * DD) / 256, 256>>>(Wb, Wfd, Wsd);

    // 1) q,k,v projections -> fp16 per-head layout
    gemm_qkv<<<dim3(DD / 128, TOK / 128, 3), 128, GSMEM_BYTES>>>();

    // 2) gate projections + elementwise
    gemm_one<<<dim3(1, TOK / 128, 1), 128, GSMEM_BYTES>>>(xh_, wch_, gate_, 128);
    gate_ew<<<(BH * LL) / 256, 256>>>(bfd, bsd);

    // 3) l2norm + k_beta + v_scaled + token-flux alpha (fp16 in place)
    norm_kernel<<<(BH * LL) / 8, 256>>>(Wtf1, btf1, Wtf2, btf2);

    // 4) decay scan
    scan_kernel<<<BH, 256>>>();

    // 5) KV states via tensor cores
    zeroM_kernel<<<(BH * 2 * DKK * DKK + 255) / 256, 256>>>();
    mstate_kernel<<<dim3(NCH, BH), 128>>>();

    // 6) output blend via tensor cores (fp16 o)
    out_kernel<<<dim3(LL / 128, BH), 128>>>();

    // 7) final projection
    gemm_one<<<dim3(DD / 128, TOK / 128, 1), 128, GSMEM_BYTES>>>(oh_, wh_ + 3 * (size_t)DD * DD, out, DD);
}